// round 1
// baseline (speedup 1.0000x reference)
#include <cuda_runtime.h>

// ---------------- problem constants ----------------
#define BB     2
#define LLEN   2048
#define DMODEL 1536
#define HH     12
#define FDIM   16
#define DVDIM  128
#define D2     256
#define CH     128
#define NC     (LLEN / CH)      // 16
#define NTOK   (BB * LLEN)      // 4096
#define QKDIM  (HH * FDIM)      // 192
#define LN_EPS 1e-5f
#define EPS    1e-12f

// ---------------- scratch (device globals; no allocations allowed) -------
__device__ float g_q [NTOK * QKDIM];                       // (b,l,h*fd) pre/post LN
__device__ float g_k [NTOK * QKDIM];
__device__ float g_v [(size_t)NTOK * DMODEL];              // (b,l,h*dv)
__device__ float g_q2[(size_t)BB * HH * LLEN * D2];        // (b,h,l,d2)
__device__ float g_k2[(size_t)BB * HH * LLEN * D2];
__device__ float g_S [(size_t)BB * HH * NC * D2 * DVDIM];  // per-chunk state (then excl prefix)
__device__ float g_z [(size_t)BB * HH * NC * D2];
__device__ float g_A [(size_t)BB * HH * NC * CH * CH];     // masked intra-chunk scores
__device__ float g_den[(size_t)BB * HH * NC * CH];
__device__ float g_oh[(size_t)NTOK * DMODEL];              // head outputs (b,l,h*dv)

// ---------------- generic SGEMM: C[M,N] = A[M,K] @ B[K,N] row-major -------
// BM=128, BN=128, BK=8, 256 threads, 8x8 register tile. M%128==0, K%8==0, N guarded.
__global__ __launch_bounds__(256) void sgemm128(const float* __restrict__ A,
                                                const float* __restrict__ B,
                                                float* __restrict__ C,
                                                int M, int N, int K) {
    __shared__ __align__(16) float sA[8][128];
    __shared__ __align__(16) float sB[8][128];
    const int tid = threadIdx.x;
    const int tx = tid & 15, ty = tid >> 4;
    const int m0 = blockIdx.y << 7, n0 = blockIdx.x << 7;
    const int ar = tid >> 1, ak = (tid & 1) << 2;   // A: 128 rows x 8 cols
    const int br = tid >> 5, bn = (tid & 31) << 2;  // B: 8 rows x 128 cols
    float acc[8][8] = {};
    for (int k0 = 0; k0 < K; k0 += 8) {
        float4 av = *(const float4*)(A + (size_t)(m0 + ar) * K + k0 + ak);
        sA[ak + 0][ar] = av.x; sA[ak + 1][ar] = av.y;
        sA[ak + 2][ar] = av.z; sA[ak + 3][ar] = av.w;
        if (n0 + bn + 3 < N) {
            *(float4*)&sB[br][bn] = *(const float4*)(B + (size_t)(k0 + br) * N + n0 + bn);
        } else {
            #pragma unroll
            for (int j = 0; j < 4; ++j)
                sB[br][bn + j] = (n0 + bn + j < N) ? B[(size_t)(k0 + br) * N + n0 + bn + j] : 0.f;
        }
        __syncthreads();
        #pragma unroll
        for (int kk = 0; kk < 8; ++kk) {
            float rm[8], rn[8];
            #pragma unroll
            for (int i = 0; i < 8; ++i) rm[i] = sA[kk][ty * 8 + i];
            #pragma unroll
            for (int j = 0; j < 8; ++j) rn[j] = sB[kk][tx * 8 + j];
            #pragma unroll
            for (int i = 0; i < 8; ++i)
                #pragma unroll
                for (int j = 0; j < 8; ++j) acc[i][j] = fmaf(rm[i], rn[j], acc[i][j]);
        }
        __syncthreads();
    }
    #pragma unroll
    for (int i = 0; i < 8; ++i) {
        const int m = m0 + ty * 8 + i;
        const int nb = n0 + tx * 8;
        if (nb + 7 < N) {
            *(float4*)(C + (size_t)m * N + nb)     = make_float4(acc[i][0], acc[i][1], acc[i][2], acc[i][3]);
            *(float4*)(C + (size_t)m * N + nb + 4) = make_float4(acc[i][4], acc[i][5], acc[i][6], acc[i][7]);
        } else {
            #pragma unroll
            for (int j = 0; j < 8; ++j)
                if (nb + j < N) C[(size_t)m * N + nb + j] = acc[i][j];
        }
    }
}

// ---------------- LayerNorm over 192 dims, in place on g_q / g_k ---------
__global__ __launch_bounds__(256) void ln_kernel(const float* __restrict__ gq,
                                                 const float* __restrict__ bq,
                                                 const float* __restrict__ gk,
                                                 const float* __restrict__ bk) {
    const int warp = (blockIdx.x * blockDim.x + threadIdx.x) >> 5;
    const int lane = threadIdx.x & 31;
    if (warp >= 2 * NTOK) return;
    const bool isq = warp < NTOK;
    float* p = isq ? (g_q + (size_t)warp * QKDIM)
                   : (g_k + (size_t)(warp - NTOK) * QKDIM);
    const float* gg = isq ? gq : gk;
    const float* bb = isq ? bq : bk;
    float x[6];
    float s = 0.f, s2 = 0.f;
    #pragma unroll
    for (int i = 0; i < 6; ++i) {
        x[i] = p[lane + 32 * i];
        s += x[i];
        s2 = fmaf(x[i], x[i], s2);
    }
    #pragma unroll
    for (int o = 16; o > 0; o >>= 1) {
        s  += __shfl_xor_sync(0xffffffffu, s,  o);
        s2 += __shfl_xor_sync(0xffffffffu, s2, o);
    }
    const float mu  = s * (1.f / QKDIM);
    const float var = s2 * (1.f / QKDIM) - mu * mu;
    const float r = rsqrtf(var + LN_EPS);
    #pragma unroll
    for (int i = 0; i < 6; ++i) {
        const int c = lane + 32 * i;
        p[c] = (x[i] - mu) * r * gg[c] + bb[c];
    }
}

// ---------------- Taylor feature expansion: q2/k2 = outer(x,x)/4 ---------
__global__ __launch_bounds__(256) void feat_kernel() {
    const int bhl = blockIdx.x;            // (b*H + h)*L + l
    const int l = bhl % LLEN;
    const int bh = bhl / LLEN;
    const int h = bh % HH;
    const int b = bh / HH;
    __shared__ float qs[16], ks[16];
    const int t = threadIdx.x;
    if (t < 16)       qs[t]      = g_q[(size_t)(b * LLEN + l) * QKDIM + h * FDIM + t];
    else if (t < 32)  ks[t - 16] = g_k[(size_t)(b * LLEN + l) * QKDIM + h * FDIM + (t - 16)];
    __syncthreads();
    const int i = t >> 4, j = t & 15;
    const size_t base = ((size_t)bh * LLEN + l) * D2 + t;
    g_q2[base] = qs[i] * qs[j] * 0.25f;
    g_k2[base] = ks[i] * ks[j] * 0.25f;
}

// ---------------- per-chunk local state: S_c = k2_c^T @ v_c, z_c = sum k2_c
// grid.x = B*H*NC*2 (2 halves of D2), 256 threads, 128x128x(K=128) GEMM
__global__ __launch_bounds__(256) void kvstate_kernel() {
    const int gx = blockIdx.x;
    const int dhalf = gx & 1;
    const int rest = gx >> 1;
    const int ch = rest % NC;
    const int bh = rest / NC;
    const int b = bh / HH, h = bh % HH;
    const int d0 = dhalf << 7;

    __shared__ __align__(16) float sK[8][128];   // [c-row][d]
    __shared__ __align__(16) float sV[8][128];   // [c-row][v]
    const int tid = threadIdx.x;
    const int tx = tid & 15, ty = tid >> 4;
    const int lc = tid >> 5, lv = (tid & 31) << 2;

    const float* k2b = g_k2 + ((size_t)bh * LLEN + ch * CH) * D2;
    const float* vb  = g_v  + ((size_t)(b * LLEN + ch * CH)) * DMODEL + h * DVDIM;

    float acc[8][8] = {};
    float zacc = 0.f;
    for (int c0 = 0; c0 < CH; c0 += 8) {
        *(float4*)&sK[lc][lv] = *(const float4*)(k2b + (size_t)(c0 + lc) * D2 + d0 + lv);
        *(float4*)&sV[lc][lv] = *(const float4*)(vb  + (size_t)(c0 + lc) * DMODEL + lv);
        __syncthreads();
        #pragma unroll
        for (int kk = 0; kk < 8; ++kk) {
            float rm[8], rn[8];
            #pragma unroll
            for (int i = 0; i < 8; ++i) rm[i] = sK[kk][ty * 8 + i];
            #pragma unroll
            for (int j = 0; j < 8; ++j) rn[j] = sV[kk][tx * 8 + j];
            #pragma unroll
            for (int i = 0; i < 8; ++i)
                #pragma unroll
                for (int j = 0; j < 8; ++j) acc[i][j] = fmaf(rm[i], rn[j], acc[i][j]);
        }
        if (tid < 128) {
            #pragma unroll
            for (int kk = 0; kk < 8; ++kk) zacc += sK[kk][tid];
        }
        __syncthreads();
    }
    float* Sout = g_S + (((size_t)bh * NC + ch) * D2 + d0) * DVDIM;
    #pragma unroll
    for (int i = 0; i < 8; ++i) {
        const int d = ty * 8 + i;
        *(float4*)(Sout + (size_t)d * DVDIM + tx * 8)     = make_float4(acc[i][0], acc[i][1], acc[i][2], acc[i][3]);
        *(float4*)(Sout + (size_t)d * DVDIM + tx * 8 + 4) = make_float4(acc[i][4], acc[i][5], acc[i][6], acc[i][7]);
    }
    if (tid < 128) g_z[((size_t)bh * NC + ch) * D2 + d0 + tid] = zacc;
}

// ---------------- exclusive prefix over chunks (S and z in place) --------
__global__ __launch_bounds__(256) void prefix_kernel() {
    const int NS = BB * HH * D2 * DVDIM;   // 786432
    const int NZ = BB * HH * D2;           // 6144
    const int idx = blockIdx.x * blockDim.x + threadIdx.x;
    if (idx < NS) {
        const int bh = idx / (D2 * DVDIM);
        const int rem = idx % (D2 * DVDIM);
        const size_t base = (size_t)bh * NC * D2 * DVDIM + rem;
        float run = 0.f;
        #pragma unroll
        for (int c = 0; c < NC; ++c) {
            const size_t p = base + (size_t)c * (D2 * DVDIM);
            const float t = g_S[p];
            g_S[p] = run;
            run += t;
        }
    } else if (idx < NS + NZ) {
        const int j = idx - NS;
        const int bh = j / D2;
        const int rem = j % D2;
        const size_t base = (size_t)bh * NC * D2 + rem;
        float run = 0.f;
        #pragma unroll
        for (int c = 0; c < NC; ++c) {
            const size_t p = base + (size_t)c * D2;
            const float t = g_z[p];
            g_z[p] = run;
            run += t;
        }
    }
}

// ---------------- attention A: A = mask(q2 @ k2^T), den = q2.z + rowsum(A)
// grid.x = B*H*NC, 256 threads, 128x128x(K=256)
__global__ __launch_bounds__(256) void attn_a_kernel() {
    const int gx = blockIdx.x;
    const int ch = gx % NC;
    const int bh = gx / NC;
    const int tid = threadIdx.x;
    const int tx = tid & 15, ty = tid >> 4;

    const float* q2b = g_q2 + ((size_t)bh * LLEN + ch * CH) * D2;
    const float* k2b = g_k2 + ((size_t)bh * LLEN + ch * CH) * D2;
    const float* zb  = g_z  + ((size_t)bh * NC + ch) * D2;

    __shared__ __align__(16) float sQ[8][128];
    __shared__ __align__(16) float sK[8][128];
    __shared__ float zs[D2];
    __shared__ float rs[CH];

    zs[tid] = zb[tid];
    const int lr = tid >> 1, lk = (tid & 1) << 2;

    float acc[8][8] = {};
    float dacc = 0.f;
    for (int d0 = 0; d0 < D2; d0 += 8) {
        float4 qv = *(const float4*)(q2b + (size_t)lr * D2 + d0 + lk);
        sQ[lk + 0][lr] = qv.x; sQ[lk + 1][lr] = qv.y;
        sQ[lk + 2][lr] = qv.z; sQ[lk + 3][lr] = qv.w;
        float4 kv = *(const float4*)(k2b + (size_t)lr * D2 + d0 + lk);
        sK[lk + 0][lr] = kv.x; sK[lk + 1][lr] = kv.y;
        sK[lk + 2][lr] = kv.z; sK[lk + 3][lr] = kv.w;
        __syncthreads();
        #pragma unroll
        for (int kk = 0; kk < 8; ++kk) {
            float rm[8], rn[8];
            #pragma unroll
            for (int i = 0; i < 8; ++i) rm[i] = sQ[kk][ty * 8 + i];
            #pragma unroll
            for (int j = 0; j < 8; ++j) rn[j] = sK[kk][tx * 8 + j];
            #pragma unroll
            for (int i = 0; i < 8; ++i)
                #pragma unroll
                for (int j = 0; j < 8; ++j) acc[i][j] = fmaf(rm[i], rn[j], acc[i][j]);
        }
        if (tid < 128) {
            #pragma unroll
            for (int kk = 0; kk < 8; ++kk) dacc = fmaf(sQ[kk][tid], zs[d0 + kk], dacc);
        }
        __syncthreads();
    }

    // causal mask, per-row sums, store A
    float* Ab = g_A + (size_t)gx * CH * CH;
    float rsum[8];
    #pragma unroll
    for (int i = 0; i < 8; ++i) {
        const int c = ty * 8 + i;
        rsum[i] = 0.f;
        #pragma unroll
        for (int j = 0; j < 8; ++j) {
            const int e = tx * 8 + j;
            const float a = (e <= c) ? acc[i][j] : 0.f;
            acc[i][j] = a;
            rsum[i] += a;
        }
    }
    #pragma unroll
    for (int i = 0; i < 8; ++i) {
        #pragma unroll
        for (int o = 8; o > 0; o >>= 1)
            rsum[i] += __shfl_xor_sync(0xffffffffu, rsum[i], o);
    }
    if (tx == 0) {
        #pragma unroll
        for (int i = 0; i < 8; ++i) rs[ty * 8 + i] = rsum[i];
    }
    #pragma unroll
    for (int i = 0; i < 8; ++i) {
        const int c = ty * 8 + i;
        *(float4*)(Ab + (size_t)c * CH + tx * 8)     = make_float4(acc[i][0], acc[i][1], acc[i][2], acc[i][3]);
        *(float4*)(Ab + (size_t)c * CH + tx * 8 + 4) = make_float4(acc[i][4], acc[i][5], acc[i][6], acc[i][7]);
    }
    __syncthreads();
    if (tid < 128) g_den[(size_t)gx * CH + tid] = dacc + rs[tid];
}

// ---------------- attention B: o = (q2 @ S + A @ v) / (den + eps) --------
// grid.x = B*H*NC, 256 threads
__global__ __launch_bounds__(256) void attn_b_kernel() {
    const int gx = blockIdx.x;
    const int ch = gx % NC;
    const int bh = gx / NC;
    const int b = bh / HH, h = bh % HH;
    const int tid = threadIdx.x;
    const int tx = tid & 15, ty = tid >> 4;

    const float* q2b = g_q2 + ((size_t)bh * LLEN + ch * CH) * D2;
    const float* Sb  = g_S  + ((size_t)bh * NC + ch) * D2 * DVDIM;
    const float* Ab  = g_A  + (size_t)gx * CH * CH;
    const float* vb  = g_v  + ((size_t)(b * LLEN + ch * CH)) * DMODEL + h * DVDIM;

    __shared__ __align__(16) float sA[8][128];
    __shared__ __align__(16) float sB[8][128];
    __shared__ float dens[CH];
    if (tid < CH) dens[tid] = g_den[(size_t)gx * CH + tid];

    const int lr = tid >> 1, lk = (tid & 1) << 2;   // row-major operand staging
    const int sr = tid >> 5, sc = (tid & 31) << 2;  // k-row operand staging

    float acc[8][8] = {};
    // phase 1: q2 @ S  (K = 256)
    for (int d0 = 0; d0 < D2; d0 += 8) {
        float4 qv = *(const float4*)(q2b + (size_t)lr * D2 + d0 + lk);
        sA[lk + 0][lr] = qv.x; sA[lk + 1][lr] = qv.y;
        sA[lk + 2][lr] = qv.z; sA[lk + 3][lr] = qv.w;
        *(float4*)&sB[sr][sc] = *(const float4*)(Sb + (size_t)(d0 + sr) * DVDIM + sc);
        __syncthreads();
        #pragma unroll
        for (int kk = 0; kk < 8; ++kk) {
            float rm[8], rn[8];
            #pragma unroll
            for (int i = 0; i < 8; ++i) rm[i] = sA[kk][ty * 8 + i];
            #pragma unroll
            for (int j = 0; j < 8; ++j) rn[j] = sB[kk][tx * 8 + j];
            #pragma unroll
            for (int i = 0; i < 8; ++i)
                #pragma unroll
                for (int j = 0; j < 8; ++j) acc[i][j] = fmaf(rm[i], rn[j], acc[i][j]);
        }
        __syncthreads();
    }
    // phase 2: A @ v  (K = 128)
    for (int e0 = 0; e0 < CH; e0 += 8) {
        float4 av = *(const float4*)(Ab + (size_t)lr * CH + e0 + lk);
        sA[lk + 0][lr] = av.x; sA[lk + 1][lr] = av.y;
        sA[lk + 2][lr] = av.z; sA[lk + 3][lr] = av.w;
        *(float4*)&sB[sr][sc] = *(const float4*)(vb + (size_t)(e0 + sr) * DMODEL + sc);
        __syncthreads();
        #pragma unroll
        for (int kk = 0; kk < 8; ++kk) {
            float rm[8], rn[8];
            #pragma unroll
            for (int i = 0; i < 8; ++i) rm[i] = sA[kk][ty * 8 + i];
            #pragma unroll
            for (int j = 0; j < 8; ++j) rn[j] = sB[kk][tx * 8 + j];
            #pragma unroll
            for (int i = 0; i < 8; ++i)
                #pragma unroll
                for (int j = 0; j < 8; ++j) acc[i][j] = fmaf(rm[i], rn[j], acc[i][j]);
        }
        __syncthreads();
    }
    float* ob = g_oh + ((size_t)(b * LLEN + ch * CH)) * DMODEL + h * DVDIM;
    #pragma unroll
    for (int i = 0; i < 8; ++i) {
        const int c = ty * 8 + i;
        const float inv = 1.f / (dens[c] + EPS);
        *(float4*)(ob + (size_t)c * DMODEL + tx * 8) =
            make_float4(acc[i][0] * inv, acc[i][1] * inv, acc[i][2] * inv, acc[i][3] * inv);
        *(float4*)(ob + (size_t)c * DMODEL + tx * 8 + 4) =
            make_float4(acc[i][4] * inv, acc[i][5] * inv, acc[i][6] * inv, acc[i][7] * inv);
    }
}

// ---------------- host: launch pipeline ----------------
extern "C" void kernel_launch(void* const* d_in, const int* in_sizes, int n_in,
                              void* d_out, int out_size) {
    (void)in_sizes; (void)n_in; (void)out_size;
    const float* x   = (const float*)d_in[0];
    const float* Wq  = (const float*)d_in[1];
    const float* Wk  = (const float*)d_in[2];
    const float* Wv  = (const float*)d_in[3];
    const float* Wo  = (const float*)d_in[4];
    const float* lqg = (const float*)d_in[5];
    const float* lqb = (const float*)d_in[6];
    const float* lkg = (const float*)d_in[7];
    const float* lkb = (const float*)d_in[8];
    float* out = (float*)d_out;

    float *qp, *kp, *vp, *ohp;
    cudaGetSymbolAddress((void**)&qp,  g_q);
    cudaGetSymbolAddress((void**)&kp,  g_k);
    cudaGetSymbolAddress((void**)&vp,  g_v);
    cudaGetSymbolAddress((void**)&ohp, g_oh);

    // 1-3: projections
    sgemm128<<<dim3(2, 32), 256>>>(x, Wq, qp, NTOK, QKDIM, DMODEL);
    sgemm128<<<dim3(2, 32), 256>>>(x, Wk, kp, NTOK, QKDIM, DMODEL);
    sgemm128<<<dim3(12, 32), 256>>>(x, Wv, vp, NTOK, DMODEL, DMODEL);
    // 4: layernorm q/k in place
    ln_kernel<<<(2 * NTOK) / 8, 256>>>(lqg, lqb, lkg, lkb);
    // 5: taylor features
    feat_kernel<<<BB * HH * LLEN, 256>>>();
    // 6: per-chunk local state
    kvstate_kernel<<<BB * HH * NC * 2, 256>>>();
    // 7: exclusive prefix over chunks
    {
        const int total = BB * HH * D2 * DVDIM + BB * HH * D2;
        prefix_kernel<<<(total + 255) / 256, 256>>>();
    }
    // 8-9: attention
    attn_a_kernel<<<BB * HH * NC, 256>>>();
    attn_b_kernel<<<BB * HH * NC, 256>>>();
    // 10: output projection
    sgemm128<<<dim3(12, 32), 256>>>(ohp, Wo, out, NTOK, DMODEL, DMODEL);
}

// round 2
// speedup vs baseline: 3.1670x; 3.1670x over previous
#include <cuda_runtime.h>

// ---------------- problem constants ----------------
#define BB     2
#define LLEN   2048
#define DMODEL 1536
#define HH     12
#define FDIM   16
#define DVDIM  128
#define D2     256
#define CH     128
#define NC     16
#define NTOK   4096
#define QKDIM  192
#define LN_EPS 1e-5f
#define EPS    1e-12f
#define SAS    136   // smem row stride (128 + 8) -> bank = (8k + m) % 32, conflict-free

// ---------------- scratch (device globals) ----------------
__device__ float g_q [NTOK * QKDIM];
__device__ float g_k [NTOK * QKDIM];
__device__ float g_v [(size_t)NTOK * DMODEL];
__device__ float g_q2[(size_t)BB * HH * LLEN * D2];
__device__ float g_k2[(size_t)BB * HH * LLEN * D2];
__device__ float g_S [(size_t)BB * HH * NC * D2 * DVDIM];
__device__ float g_z [(size_t)BB * HH * NC * D2];
__device__ float g_A [(size_t)BB * HH * NC * CH * CH];
__device__ float g_den[(size_t)BB * HH * NC * CH];
__device__ float g_oh[(size_t)NTOK * DMODEL];

// ---------------- tf32 helpers ----------------
__device__ __forceinline__ unsigned f2tf(float x) {
    unsigned u; asm("cvt.rna.tf32.f32 %0, %1;" : "=r"(u) : "f"(x)); return u;
}
__device__ __forceinline__ void mma8(float* c, const unsigned* a, const unsigned* b) {
    asm volatile("mma.sync.aligned.m16n8k8.row.col.f32.tf32.tf32.f32 "
        "{%0,%1,%2,%3},{%4,%5,%6,%7},{%8,%9},{%0,%1,%2,%3};"
        : "+f"(c[0]), "+f"(c[1]), "+f"(c[2]), "+f"(c[3])
        : "r"(a[0]), "r"(a[1]), "r"(a[2]), "r"(a[3]), "r"(b[0]), "r"(b[1]));
}

// One BK=32 stage of warp-level MMA. sA: [k][m] (tf32 bits), sB: [k][n].
// Warp tile 64x32: 4 m-tiles of 16, 4 n-tiles of 8.
__device__ __forceinline__ void warp_mma_stage(const unsigned* __restrict__ sA,
                                               const unsigned* __restrict__ sB,
                                               int mbase, int nbase, int g, int tig,
                                               float (*acc)[4]) {
#pragma unroll
    for (int kk = 0; kk < 32; kk += 8) {
        unsigned a[4][4], b[4][2];
#pragma unroll
        for (int mt = 0; mt < 4; ++mt) {
            const unsigned* p0 = sA + (kk + tig) * SAS + mbase + mt * 16;
            const unsigned* p1 = p0 + 4 * SAS;
            a[mt][0] = p0[g]; a[mt][1] = p0[g + 8];
            a[mt][2] = p1[g]; a[mt][3] = p1[g + 8];
        }
#pragma unroll
        for (int nt = 0; nt < 4; ++nt) {
            b[nt][0] = sB[(kk + tig) * SAS + nbase + nt * 8 + g];
            b[nt][1] = sB[(kk + tig + 4) * SAS + nbase + nt * 8 + g];
        }
#pragma unroll
        for (int mt = 0; mt < 4; ++mt)
#pragma unroll
            for (int nt = 0; nt < 4; ++nt)
                mma8(acc[mt * 4 + nt], a[mt], b[nt]);
    }
}

// ---------------- generic projection GEMM: C[M,N] = A[M,K] @ B[K,N] ------
// M % 128 == 0, K % 32 == 0, N guarded (for N=192).
__global__ __launch_bounds__(256) void gemm_tf32(const float* __restrict__ A,
                                                 const float* __restrict__ B,
                                                 float* __restrict__ C,
                                                 int M, int N, int K) {
    __shared__ unsigned sA[32 * SAS];
    __shared__ unsigned sB[32 * SAS];
    const int tid = threadIdx.x;
    const int lane = tid & 31, w = tid >> 5;
    const int g = lane >> 2, tig = lane & 3;
    const int mbase = (w & 1) * 64, nbase = (w >> 1) * 32;
    const int m0 = blockIdx.y * 128, n0 = blockIdx.x * 128;

    const int arow = tid >> 1, akc = (tid & 1) * 4;     // A: 2 thr/row, 32B/row
    const int bkr = tid >> 5, bnq = (tid & 31) * 4;     // B: direct rows

    float acc[16][4];
#pragma unroll
    for (int i = 0; i < 16; ++i) acc[i][0] = acc[i][1] = acc[i][2] = acc[i][3] = 0.f;

    const bool nvalid = (n0 + bnq < N);
    float4 ra[4], rb[4];
#pragma unroll
    for (int i = 0; i < 4; ++i) {
        ra[i] = *(const float4*)(A + (size_t)(m0 + arow) * K + akc + 8 * i);
        rb[i] = nvalid ? *(const float4*)(B + (size_t)(bkr + 8 * i) * N + n0 + bnq)
                       : make_float4(0.f, 0.f, 0.f, 0.f);
    }
    const int NS = K / 32;
    for (int s = 0; s < NS; ++s) {
        __syncthreads();
#pragma unroll
        for (int i = 0; i < 4; ++i) {
            const int kc = akc + 8 * i;
            sA[(kc + 0) * SAS + arow] = f2tf(ra[i].x);
            sA[(kc + 1) * SAS + arow] = f2tf(ra[i].y);
            sA[(kc + 2) * SAS + arow] = f2tf(ra[i].z);
            sA[(kc + 3) * SAS + arow] = f2tf(ra[i].w);
            *(uint4*)&sB[(bkr + 8 * i) * SAS + bnq] =
                make_uint4(f2tf(rb[i].x), f2tf(rb[i].y), f2tf(rb[i].z), f2tf(rb[i].w));
        }
        __syncthreads();
        if (s + 1 < NS) {
            const int k0 = (s + 1) * 32;
#pragma unroll
            for (int i = 0; i < 4; ++i) {
                ra[i] = *(const float4*)(A + (size_t)(m0 + arow) * K + k0 + akc + 8 * i);
                rb[i] = nvalid ? *(const float4*)(B + (size_t)(k0 + bkr + 8 * i) * N + n0 + bnq)
                               : make_float4(0.f, 0.f, 0.f, 0.f);
            }
        }
        warp_mma_stage(sA, sB, mbase, nbase, g, tig, acc);
    }
#pragma unroll
    for (int mt = 0; mt < 4; ++mt) {
        const int r0 = m0 + mbase + mt * 16 + g;
#pragma unroll
        for (int nt = 0; nt < 4; ++nt) {
            const int col = n0 + nbase + nt * 8 + tig * 2;
            if (col < N) {
                const float* a4 = acc[mt * 4 + nt];
                *(float2*)(C + (size_t)r0 * N + col)       = make_float2(a4[0], a4[1]);
                *(float2*)(C + (size_t)(r0 + 8) * N + col) = make_float2(a4[2], a4[3]);
            }
        }
    }
}

// ---------------- LayerNorm over 192 dims, in place ----------------
__global__ __launch_bounds__(256) void ln_kernel(const float* __restrict__ gq,
                                                 const float* __restrict__ bq,
                                                 const float* __restrict__ gk,
                                                 const float* __restrict__ bk) {
    const int warp = (blockIdx.x * blockDim.x + threadIdx.x) >> 5;
    const int lane = threadIdx.x & 31;
    if (warp >= 2 * NTOK) return;
    const bool isq = warp < NTOK;
    float* p = isq ? (g_q + (size_t)warp * QKDIM) : (g_k + (size_t)(warp - NTOK) * QKDIM);
    const float* gg = isq ? gq : gk;
    const float* bb = isq ? bq : bk;
    float x[6]; float s = 0.f, s2 = 0.f;
#pragma unroll
    for (int i = 0; i < 6; ++i) { x[i] = p[lane + 32 * i]; s += x[i]; s2 = fmaf(x[i], x[i], s2); }
#pragma unroll
    for (int o = 16; o > 0; o >>= 1) {
        s += __shfl_xor_sync(0xffffffffu, s, o);
        s2 += __shfl_xor_sync(0xffffffffu, s2, o);
    }
    const float mu = s * (1.f / QKDIM);
    const float var = s2 * (1.f / QKDIM) - mu * mu;
    const float r = rsqrtf(var + LN_EPS);
#pragma unroll
    for (int i = 0; i < 6; ++i) {
        const int c = lane + 32 * i;
        p[c] = (x[i] - mu) * r * gg[c] + bb[c];
    }
}

// ---------------- Taylor features: outer(x,x)/4 ----------------
__global__ __launch_bounds__(256) void feat_kernel() {
    const int bhl = blockIdx.x;
    const int l = bhl % LLEN;
    const int bh = bhl / LLEN;
    const int h = bh % HH, b = bh / HH;
    __shared__ float qs[16], ks[16];
    const int t = threadIdx.x;
    if (t < 16)      qs[t]      = g_q[(size_t)(b * LLEN + l) * QKDIM + h * FDIM + t];
    else if (t < 32) ks[t - 16] = g_k[(size_t)(b * LLEN + l) * QKDIM + h * FDIM + (t - 16)];
    __syncthreads();
    const int i = t >> 4, j = t & 15;
    const size_t base = ((size_t)bh * LLEN + l) * D2 + t;
    g_q2[base] = qs[i] * qs[j] * 0.25f;
    g_k2[base] = ks[i] * ks[j] * 0.25f;
}

// ---------------- per-chunk state: S_c = k2_c^T v_c, z_c = sum k2_c ------
// grid = B*H*NC*2 (d-halves). M=128(d), N=128(v), K=128(c). Both operands direct.
__global__ __launch_bounds__(256) void kvstate_tf32() {
    __shared__ unsigned sA[32 * SAS];
    __shared__ unsigned sB[32 * SAS];
    const int gx = blockIdx.x;
    const int dhalf = gx & 1;
    const int rest = gx >> 1;
    const int ch = rest % NC;
    const int bh = rest / NC;
    const int b = bh / HH, h = bh % HH;
    const int d0 = dhalf * 128;

    const float* k2b = g_k2 + ((size_t)bh * LLEN + ch * CH) * D2;
    const float* vb  = g_v  + (size_t)(b * LLEN + ch * CH) * DMODEL + h * DVDIM;

    const int tid = threadIdx.x;
    const int lane = tid & 31, w = tid >> 5;
    const int g = lane >> 2, tig = lane & 3;
    const int mbase = (w & 1) * 64, nbase = (w >> 1) * 32;
    const int kr = tid >> 5, nq = (tid & 31) * 4;

    float acc[16][4];
#pragma unroll
    for (int i = 0; i < 16; ++i) acc[i][0] = acc[i][1] = acc[i][2] = acc[i][3] = 0.f;
    float zacc = 0.f;

    float4 ra[4], rb[4];
#pragma unroll
    for (int i = 0; i < 4; ++i) {
        ra[i] = *(const float4*)(k2b + (size_t)(kr + 8 * i) * D2 + d0 + nq);
        rb[i] = *(const float4*)(vb + (size_t)(kr + 8 * i) * DMODEL + nq);
    }
    for (int s = 0; s < 4; ++s) {
        __syncthreads();
#pragma unroll
        for (int i = 0; i < 4; ++i) {
            *(uint4*)&sA[(kr + 8 * i) * SAS + nq] =
                make_uint4(f2tf(ra[i].x), f2tf(ra[i].y), f2tf(ra[i].z), f2tf(ra[i].w));
            *(uint4*)&sB[(kr + 8 * i) * SAS + nq] =
                make_uint4(f2tf(rb[i].x), f2tf(rb[i].y), f2tf(rb[i].z), f2tf(rb[i].w));
        }
        __syncthreads();
        if (s + 1 < 4) {
            const int c0 = (s + 1) * 32;
#pragma unroll
            for (int i = 0; i < 4; ++i) {
                ra[i] = *(const float4*)(k2b + (size_t)(c0 + kr + 8 * i) * D2 + d0 + nq);
                rb[i] = *(const float4*)(vb + (size_t)(c0 + kr + 8 * i) * DMODEL + nq);
            }
        }
        if (tid < 128) {
#pragma unroll
            for (int r = 0; r < 32; ++r) zacc += __uint_as_float(sA[r * SAS + tid]);
        }
        warp_mma_stage(sA, sB, mbase, nbase, g, tig, acc);
    }
    float* Sout = g_S + (((size_t)bh * NC + ch) * D2 + d0) * DVDIM;
#pragma unroll
    for (int mt = 0; mt < 4; ++mt) {
        const int r0 = mbase + mt * 16 + g;
#pragma unroll
        for (int nt = 0; nt < 4; ++nt) {
            const int col = nbase + nt * 8 + tig * 2;
            const float* a4 = acc[mt * 4 + nt];
            *(float2*)(Sout + (size_t)r0 * DVDIM + col)       = make_float2(a4[0], a4[1]);
            *(float2*)(Sout + (size_t)(r0 + 8) * DVDIM + col) = make_float2(a4[2], a4[3]);
        }
    }
    if (tid < 128) g_z[((size_t)bh * NC + ch) * D2 + d0 + tid] = zacc;
}

// ---------------- exclusive prefix over chunks ----------------
__global__ __launch_bounds__(256) void prefix_kernel() {
    const int NS = BB * HH * D2 * DVDIM;
    const int NZ = BB * HH * D2;
    const int idx = blockIdx.x * blockDim.x + threadIdx.x;
    if (idx < NS) {
        const int bh = idx / (D2 * DVDIM);
        const int rem = idx % (D2 * DVDIM);
        const size_t base = (size_t)bh * NC * D2 * DVDIM + rem;
        float run = 0.f;
#pragma unroll
        for (int c = 0; c < NC; ++c) {
            const size_t p = base + (size_t)c * (D2 * DVDIM);
            const float t = g_S[p]; g_S[p] = run; run += t;
        }
    } else if (idx < NS + NZ) {
        const int j = idx - NS;
        const int bh = j / D2, rem = j % D2;
        const size_t base = (size_t)bh * NC * D2 + rem;
        float run = 0.f;
#pragma unroll
        for (int c = 0; c < NC; ++c) {
            const size_t p = base + (size_t)c * D2;
            const float t = g_z[p]; g_z[p] = run; run += t;
        }
    }
}

// ---------------- attention A: A = mask(q2 k2^T), den = q2.z + rowsum ----
// M=128(c), N=128(e), K=256(d). Both operands transposed staging.
__global__ __launch_bounds__(256) void attn_a_tf32() {
    __shared__ unsigned sA[32 * SAS];
    __shared__ unsigned sB[32 * SAS];
    __shared__ float zs[D2];
    __shared__ float rsp[4][128];
    const int gx = blockIdx.x;
    const int ch = gx % NC, bh = gx / NC;
    const float* q2b = g_q2 + ((size_t)bh * LLEN + ch * CH) * D2;
    const float* k2b = g_k2 + ((size_t)bh * LLEN + ch * CH) * D2;
    const float* zb  = g_z  + ((size_t)bh * NC + ch) * D2;

    const int tid = threadIdx.x;
    const int lane = tid & 31, w = tid >> 5;
    const int g = lane >> 2, tig = lane & 3;
    const int mbase = (w & 1) * 64, nbase = (w >> 1) * 32;
    const int arow = tid >> 1, akc = (tid & 1) * 4;

    zs[tid] = zb[tid];

    float acc[16][4];
#pragma unroll
    for (int i = 0; i < 16; ++i) acc[i][0] = acc[i][1] = acc[i][2] = acc[i][3] = 0.f;
    float dacc = 0.f;

    float4 ra[4], rb[4];
#pragma unroll
    for (int i = 0; i < 4; ++i) {
        ra[i] = *(const float4*)(q2b + (size_t)arow * D2 + akc + 8 * i);
        rb[i] = *(const float4*)(k2b + (size_t)arow * D2 + akc + 8 * i);
    }
    for (int s = 0; s < 8; ++s) {
        __syncthreads();
#pragma unroll
        for (int i = 0; i < 4; ++i) {
            const int kc = akc + 8 * i;
            sA[(kc + 0) * SAS + arow] = f2tf(ra[i].x);
            sA[(kc + 1) * SAS + arow] = f2tf(ra[i].y);
            sA[(kc + 2) * SAS + arow] = f2tf(ra[i].z);
            sA[(kc + 3) * SAS + arow] = f2tf(ra[i].w);
            sB[(kc + 0) * SAS + arow] = f2tf(rb[i].x);
            sB[(kc + 1) * SAS + arow] = f2tf(rb[i].y);
            sB[(kc + 2) * SAS + arow] = f2tf(rb[i].z);
            sB[(kc + 3) * SAS + arow] = f2tf(rb[i].w);
        }
        __syncthreads();
        if (s + 1 < 8) {
            const int k0 = (s + 1) * 32;
#pragma unroll
            for (int i = 0; i < 4; ++i) {
                ra[i] = *(const float4*)(q2b + (size_t)arow * D2 + k0 + akc + 8 * i);
                rb[i] = *(const float4*)(k2b + (size_t)arow * D2 + k0 + akc + 8 * i);
            }
        }
        if (tid < 128) {
#pragma unroll
            for (int r = 0; r < 32; ++r)
                dacc = fmaf(__uint_as_float(sA[r * SAS + tid]), zs[s * 32 + r], dacc);
        }
        warp_mma_stage(sA, sB, mbase, nbase, g, tig, acc);
    }
    // mask + rowsum + store A
    float* Ab = g_A + (size_t)gx * CH * CH;
#pragma unroll
    for (int mt = 0; mt < 4; ++mt) {
        const int r0 = mbase + mt * 16 + g;
        const int r1 = r0 + 8;
        float rs0 = 0.f, rs1 = 0.f;
#pragma unroll
        for (int nt = 0; nt < 4; ++nt) {
            const int col = nbase + nt * 8 + tig * 2;
            const float* a4 = acc[mt * 4 + nt];
            const float v00 = (col     <= r0) ? a4[0] : 0.f;
            const float v01 = (col + 1 <= r0) ? a4[1] : 0.f;
            const float v10 = (col     <= r1) ? a4[2] : 0.f;
            const float v11 = (col + 1 <= r1) ? a4[3] : 0.f;
            rs0 += v00 + v01; rs1 += v10 + v11;
            *(float2*)(Ab + (size_t)r0 * CH + col) = make_float2(v00, v01);
            *(float2*)(Ab + (size_t)r1 * CH + col) = make_float2(v10, v11);
        }
        rs0 += __shfl_xor_sync(0xffffffffu, rs0, 1);
        rs0 += __shfl_xor_sync(0xffffffffu, rs0, 2);
        rs1 += __shfl_xor_sync(0xffffffffu, rs1, 1);
        rs1 += __shfl_xor_sync(0xffffffffu, rs1, 2);
        if (tig == 0) { rsp[w >> 1][r0] = rs0; rsp[w >> 1][r1] = rs1; }
    }
    __syncthreads();
    if (tid < 128)
        g_den[(size_t)gx * CH + tid] = dacc + rsp[0][tid] + rsp[1][tid] + rsp[2][tid] + rsp[3][tid];
}

// ---------------- attention B: o = (q2 S + A v) / (den + eps) ----------
__global__ __launch_bounds__(256) void attn_b_tf32() {
    __shared__ unsigned sA[32 * SAS];
    __shared__ unsigned sB[32 * SAS];
    __shared__ float dens[CH];
    const int gx = blockIdx.x;
    const int ch = gx % NC, bh = gx / NC;
    const int b = bh / HH, h = bh % HH;
    const float* q2b = g_q2 + ((size_t)bh * LLEN + ch * CH) * D2;
    const float* Sb  = g_S  + ((size_t)bh * NC + ch) * D2 * DVDIM;
    const float* Ab  = g_A  + (size_t)gx * CH * CH;
    const float* vb  = g_v  + (size_t)(b * LLEN + ch * CH) * DMODEL + h * DVDIM;

    const int tid = threadIdx.x;
    const int lane = tid & 31, w = tid >> 5;
    const int g = lane >> 2, tig = lane & 3;
    const int mbase = (w & 1) * 64, nbase = (w >> 1) * 32;
    const int arow = tid >> 1, akc = (tid & 1) * 4;
    const int bkr = tid >> 5, bnq = (tid & 31) * 4;

    if (tid < CH) dens[tid] = g_den[(size_t)gx * CH + tid];

    float acc[16][4];
#pragma unroll
    for (int i = 0; i < 16; ++i) acc[i][0] = acc[i][1] = acc[i][2] = acc[i][3] = 0.f;

    float4 ra[4], rb[4];
    // phase 1: q2 @ S, K = 256
#pragma unroll
    for (int i = 0; i < 4; ++i) {
        ra[i] = *(const float4*)(q2b + (size_t)arow * D2 + akc + 8 * i);
        rb[i] = *(const float4*)(Sb + (size_t)(bkr + 8 * i) * DVDIM + bnq);
    }
    for (int s = 0; s < 8; ++s) {
        __syncthreads();
#pragma unroll
        for (int i = 0; i < 4; ++i) {
            const int kc = akc + 8 * i;
            sA[(kc + 0) * SAS + arow] = f2tf(ra[i].x);
            sA[(kc + 1) * SAS + arow] = f2tf(ra[i].y);
            sA[(kc + 2) * SAS + arow] = f2tf(ra[i].z);
            sA[(kc + 3) * SAS + arow] = f2tf(ra[i].w);
            *(uint4*)&sB[(bkr + 8 * i) * SAS + bnq] =
                make_uint4(f2tf(rb[i].x), f2tf(rb[i].y), f2tf(rb[i].z), f2tf(rb[i].w));
        }
        __syncthreads();
        if (s + 1 < 8) {
            const int k0 = (s + 1) * 32;
#pragma unroll
            for (int i = 0; i < 4; ++i) {
                ra[i] = *(const float4*)(q2b + (size_t)arow * D2 + k0 + akc + 8 * i);
                rb[i] = *(const float4*)(Sb + (size_t)(k0 + bkr + 8 * i) * DVDIM + bnq);
            }
        }
        warp_mma_stage(sA, sB, mbase, nbase, g, tig, acc);
    }
    // phase 2: A @ v, K = 128
#pragma unroll
    for (int i = 0; i < 4; ++i) {
        ra[i] = *(const float4*)(Ab + (size_t)arow * CH + akc + 8 * i);
        rb[i] = *(const float4*)(vb + (size_t)(bkr + 8 * i) * DMODEL + bnq);
    }
    for (int s = 0; s < 4; ++s) {
        __syncthreads();
#pragma unroll
        for (int i = 0; i < 4; ++i) {
            const int kc = akc + 8 * i;
            sA[(kc + 0) * SAS + arow] = f2tf(ra[i].x);
            sA[(kc + 1) * SAS + arow] = f2tf(ra[i].y);
            sA[(kc + 2) * SAS + arow] = f2tf(ra[i].z);
            sA[(kc + 3) * SAS + arow] = f2tf(ra[i].w);
            *(uint4*)&sB[(bkr + 8 * i) * SAS + bnq] =
                make_uint4(f2tf(rb[i].x), f2tf(rb[i].y), f2tf(rb[i].z), f2tf(rb[i].w));
        }
        __syncthreads();
        if (s + 1 < 4) {
            const int k0 = (s + 1) * 32;
#pragma unroll
            for (int i = 0; i < 4; ++i) {
                ra[i] = *(const float4*)(Ab + (size_t)arow * CH + k0 + akc + 8 * i);
                rb[i] = *(const float4*)(vb + (size_t)(k0 + bkr + 8 * i) * DMODEL + bnq);
            }
        }
        warp_mma_stage(sA, sB, mbase, nbase, g, tig, acc);
    }
    float* ob = g_oh + (size_t)(b * LLEN + ch * CH) * DMODEL + h * DVDIM;
#pragma unroll
    for (int mt = 0; mt < 4; ++mt) {
        const int r0 = mbase + mt * 16 + g;
        const float inv0 = 1.f / (dens[r0] + EPS);
        const float inv1 = 1.f / (dens[r0 + 8] + EPS);
#pragma unroll
        for (int nt = 0; nt < 4; ++nt) {
            const int col = nbase + nt * 8 + tig * 2;
            const float* a4 = acc[mt * 4 + nt];
            *(float2*)(ob + (size_t)r0 * DMODEL + col)       = make_float2(a4[0] * inv0, a4[1] * inv0);
            *(float2*)(ob + (size_t)(r0 + 8) * DMODEL + col) = make_float2(a4[2] * inv1, a4[3] * inv1);
        }
    }
}

// ---------------- host pipeline ----------------
extern "C" void kernel_launch(void* const* d_in, const int* in_sizes, int n_in,
                              void* d_out, int out_size) {
    (void)in_sizes; (void)n_in; (void)out_size;
    const float* x   = (const float*)d_in[0];
    const float* Wq  = (const float*)d_in[1];
    const float* Wk  = (const float*)d_in[2];
    const float* Wv  = (const float*)d_in[3];
    const float* Wo  = (const float*)d_in[4];
    const float* lqg = (const float*)d_in[5];
    const float* lqb = (const float*)d_in[6];
    const float* lkg = (const float*)d_in[7];
    const float* lkb = (const float*)d_in[8];
    float* out = (float*)d_out;

    float *qp, *kp, *vp, *ohp;
    cudaGetSymbolAddress((void**)&qp, g_q);
    cudaGetSymbolAddress((void**)&kp, g_k);
    cudaGetSymbolAddress((void**)&vp, g_v);
    cudaGetSymbolAddress((void**)&ohp, g_oh);

    gemm_tf32<<<dim3(2, 32), 256>>>(x, Wq, qp, NTOK, QKDIM, DMODEL);
    gemm_tf32<<<dim3(2, 32), 256>>>(x, Wk, kp, NTOK, QKDIM, DMODEL);
    gemm_tf32<<<dim3(12, 32), 256>>>(x, Wv, vp, NTOK, DMODEL, DMODEL);
    ln_kernel<<<(2 * NTOK) / 8, 256>>>(lqg, lqb, lkg, lkb);
    feat_kernel<<<BB * HH * LLEN, 256>>>();
    kvstate_tf32<<<BB * HH * NC * 2, 256>>>();
    {
        const int total = BB * HH * D2 * DVDIM + BB * HH * D2;
        prefix_kernel<<<(total + 255) / 256, 256>>>();
    }
    attn_a_tf32<<<BB * HH * NC, 256>>>();
    attn_b_tf32<<<BB * HH * NC, 256>>>();
    gemm_tf32<<<dim3(12, 32), 256>>>(ohp, Wo, out, NTOK, DMODEL, DMODEL);
}

// round 3
// speedup vs baseline: 3.2484x; 1.0257x over previous
#include <cuda_runtime.h>
#include <cuda_bf16.h>

// ---------------- problem constants ----------------
#define BB     2
#define LLEN   2048
#define DMODEL 1536
#define HH     12
#define FDIM   16
#define DVDIM  128
#define D2     256
#define CH     128
#define NC     16
#define NTOK   4096
#define QKDIM  192
#define LN_EPS 1e-5f
#define EPS    1e-12f
#define SAS    136   // smem row stride in 4B units -> conflict-free fragment loads

// ---------------- scratch (device globals) ----------------
__device__ float g_q [NTOK * QKDIM];
__device__ float g_k [NTOK * QKDIM];
__device__ float g_v [(size_t)NTOK * DMODEL];
__device__ float g_S [(size_t)BB * HH * NC * D2 * DVDIM];
__device__ float g_z [(size_t)BB * HH * NC * D2];
__device__ float g_A [(size_t)BB * HH * NC * CH * CH];
__device__ float g_den[(size_t)BB * HH * NC * CH];
__device__ float g_oh[(size_t)NTOK * DMODEL];

// ---------------- bf16 split helpers ----------------
// pack (x,y) -> bf16x2 hi, and residual bf16x2 lo.  low 16 bits = x (lower k).
__device__ __forceinline__ void split2(float x, float y, unsigned& h, unsigned& l) {
    __nv_bfloat162 hh = __floats2bfloat162_rn(x, y);
    float rx = x - __low2float(hh);
    float ry = y - __high2float(hh);
    __nv_bfloat162 ll = __floats2bfloat162_rn(rx, ry);
    h = *reinterpret_cast<unsigned*>(&hh);
    l = *reinterpret_cast<unsigned*>(&ll);
}

__device__ __forceinline__ void mma16(float* c, const unsigned* a, const unsigned* b) {
    asm volatile("mma.sync.aligned.m16n8k16.row.col.f32.bf16.bf16.f32 "
        "{%0,%1,%2,%3},{%4,%5,%6,%7},{%8,%9},{%0,%1,%2,%3};"
        : "+f"(c[0]), "+f"(c[1]), "+f"(c[2]), "+f"(c[3])
        : "r"(a[0]), "r"(a[1]), "r"(a[2]), "r"(a[3]), "r"(b[0]), "r"(b[1]));
}

// One BK=32 stage (16 kp-rows) of 3-term split MMA. Warp tile 64x32.
// smem layout: [kp][m or n], kp = k/2, each entry bf16x2 (k even in low bits).
__device__ __forceinline__ void warp_mma3(const unsigned* __restrict__ sAh,
                                          const unsigned* __restrict__ sAl,
                                          const unsigned* __restrict__ sBh,
                                          const unsigned* __restrict__ sBl,
                                          int mbase, int nbase, int g, int t,
                                          float (*acc)[4]) {
#pragma unroll
    for (int o = 0; o < 16; o += 8) {
        const int r0 = (o + t) * SAS, r1 = (o + t + 4) * SAS;
        unsigned ah[4][4], al[4][4], bh[4][2], bl[4][2];
#pragma unroll
        for (int mt = 0; mt < 4; ++mt) {
            const int m = mbase + mt * 16 + g;
            ah[mt][0] = sAh[r0 + m]; ah[mt][1] = sAh[r0 + m + 8];
            ah[mt][2] = sAh[r1 + m]; ah[mt][3] = sAh[r1 + m + 8];
            al[mt][0] = sAl[r0 + m]; al[mt][1] = sAl[r0 + m + 8];
            al[mt][2] = sAl[r1 + m]; al[mt][3] = sAl[r1 + m + 8];
        }
#pragma unroll
        for (int nt = 0; nt < 4; ++nt) {
            const int n = nbase + nt * 8 + g;
            bh[nt][0] = sBh[r0 + n]; bh[nt][1] = sBh[r1 + n];
            bl[nt][0] = sBl[r0 + n]; bl[nt][1] = sBl[r1 + n];
        }
#pragma unroll
        for (int mt = 0; mt < 4; ++mt)
#pragma unroll
            for (int nt = 0; nt < 4; ++nt) {
                mma16(acc[mt * 4 + nt], ah[mt], bh[nt]);
                mma16(acc[mt * 4 + nt], al[mt], bh[nt]);
                mma16(acc[mt * 4 + nt], ah[mt], bl[nt]);
            }
    }
}

// ---------------- generic projection GEMM core (bf16x3) ----------------
__device__ __forceinline__ void gemm_core(const float* __restrict__ A,
                                          const float* __restrict__ B,
                                          float* __restrict__ C,
                                          int N, int K, int m0, int n0,
                                          unsigned* sAh, unsigned* sAl,
                                          unsigned* sBh, unsigned* sBl) {
    const int tid = threadIdx.x;
    const int lane = tid & 31, w = tid >> 5;
    const int g = lane >> 2, t = lane & 3;
    const int mbase = (w & 1) * 64, nbase = (w >> 1) * 32;
    const int arow = tid >> 1, akc = (tid & 1) * 4;
    const int pkr = tid >> 4, bn = (tid & 15) * 8;
    const bool bval = (n0 + bn) < N;

    float acc[16][4];
#pragma unroll
    for (int i = 0; i < 16; ++i) acc[i][0] = acc[i][1] = acc[i][2] = acc[i][3] = 0.f;

    float4 ra[4], rb[4];
#pragma unroll
    for (int i = 0; i < 4; ++i)
        ra[i] = *(const float4*)(A + (size_t)(m0 + arow) * K + akc + 8 * i);
    if (bval) {
        rb[0] = *(const float4*)(B + (size_t)(2 * pkr) * N + n0 + bn);
        rb[1] = *(const float4*)(B + (size_t)(2 * pkr) * N + n0 + bn + 4);
        rb[2] = *(const float4*)(B + (size_t)(2 * pkr + 1) * N + n0 + bn);
        rb[3] = *(const float4*)(B + (size_t)(2 * pkr + 1) * N + n0 + bn + 4);
    } else {
        rb[0] = rb[1] = rb[2] = rb[3] = make_float4(0.f, 0.f, 0.f, 0.f);
    }

    const int NSt = K >> 5;
    for (int s = 0; s < NSt; ++s) {
        __syncthreads();
#pragma unroll
        for (int i = 0; i < 4; ++i) {
            const int kp = (tid & 1) * 2 + 4 * i;
            unsigned h0, l0, h1, l1;
            split2(ra[i].x, ra[i].y, h0, l0);
            split2(ra[i].z, ra[i].w, h1, l1);
            sAh[kp * SAS + arow] = h0;       sAl[kp * SAS + arow] = l0;
            sAh[(kp + 1) * SAS + arow] = h1; sAl[(kp + 1) * SAS + arow] = l1;
        }
        {
            const float* e0 = (const float*)&rb[0];
            const float* e1 = (const float*)&rb[2];
            unsigned hh[8], ll[8];
#pragma unroll
            for (int e = 0; e < 8; ++e) split2(e0[e], e1[e], hh[e], ll[e]);
            *(uint4*)&sBh[pkr * SAS + bn]     = make_uint4(hh[0], hh[1], hh[2], hh[3]);
            *(uint4*)&sBh[pkr * SAS + bn + 4] = make_uint4(hh[4], hh[5], hh[6], hh[7]);
            *(uint4*)&sBl[pkr * SAS + bn]     = make_uint4(ll[0], ll[1], ll[2], ll[3]);
            *(uint4*)&sBl[pkr * SAS + bn + 4] = make_uint4(ll[4], ll[5], ll[6], ll[7]);
        }
        __syncthreads();
        if (s + 1 < NSt) {
            const int k0 = (s + 1) * 32;
#pragma unroll
            for (int i = 0; i < 4; ++i)
                ra[i] = *(const float4*)(A + (size_t)(m0 + arow) * K + k0 + akc + 8 * i);
            if (bval) {
                rb[0] = *(const float4*)(B + (size_t)(k0 + 2 * pkr) * N + n0 + bn);
                rb[1] = *(const float4*)(B + (size_t)(k0 + 2 * pkr) * N + n0 + bn + 4);
                rb[2] = *(const float4*)(B + (size_t)(k0 + 2 * pkr + 1) * N + n0 + bn);
                rb[3] = *(const float4*)(B + (size_t)(k0 + 2 * pkr + 1) * N + n0 + bn + 4);
            }
        }
        warp_mma3(sAh, sAl, sBh, sBl, mbase, nbase, g, t, acc);
    }
#pragma unroll
    for (int mt = 0; mt < 4; ++mt) {
        const int r0 = m0 + mbase + mt * 16 + g;
#pragma unroll
        for (int nt = 0; nt < 4; ++nt) {
            const int col = n0 + nbase + nt * 8 + t * 2;
            if (col < N) {
                const float* a4 = acc[mt * 4 + nt];
                *(float2*)(C + (size_t)r0 * N + col)       = make_float2(a4[0], a4[1]);
                *(float2*)(C + (size_t)(r0 + 8) * N + col) = make_float2(a4[2], a4[3]);
            }
        }
    }
}

__global__ __launch_bounds__(256) void projqk_kernel(const float* __restrict__ x,
                                                     const float* __restrict__ Wq,
                                                     const float* __restrict__ Wk) {
    __shared__ unsigned sAh[16 * SAS], sAl[16 * SAS], sBh[16 * SAS], sBl[16 * SAS];
    const float* B = blockIdx.z ? Wk : Wq;
    float* C = blockIdx.z ? (float*)g_k : (float*)g_q;
    gemm_core(x, B, C, QKDIM, DMODEL, blockIdx.y * 128, blockIdx.x * 128, sAh, sAl, sBh, sBl);
}

__global__ __launch_bounds__(256) void proj_kernel(const float* __restrict__ A,
                                                   const float* __restrict__ B,
                                                   float* __restrict__ C, int N, int K) {
    __shared__ unsigned sAh[16 * SAS], sAl[16 * SAS], sBh[16 * SAS], sBl[16 * SAS];
    gemm_core(A, B, C, N, K, blockIdx.y * 128, blockIdx.x * 128, sAh, sAl, sBh, sBl);
}

// ---------------- LayerNorm over 192 dims, in place ----------------
__global__ __launch_bounds__(256) void ln_kernel(const float* __restrict__ gq,
                                                 const float* __restrict__ bq,
                                                 const float* __restrict__ gk,
                                                 const float* __restrict__ bk) {
    const int warp = (blockIdx.x * blockDim.x + threadIdx.x) >> 5;
    const int lane = threadIdx.x & 31;
    if (warp >= 2 * NTOK) return;
    const bool isq = warp < NTOK;
    float* p = isq ? (g_q + (size_t)warp * QKDIM) : (g_k + (size_t)(warp - NTOK) * QKDIM);
    const float* gg = isq ? gq : gk;
    const float* bb = isq ? bq : bk;
    float x[6]; float s = 0.f, s2 = 0.f;
#pragma unroll
    for (int i = 0; i < 6; ++i) { x[i] = p[lane + 32 * i]; s += x[i]; s2 = fmaf(x[i], x[i], s2); }
#pragma unroll
    for (int o = 16; o > 0; o >>= 1) {
        s += __shfl_xor_sync(0xffffffffu, s, o);
        s2 += __shfl_xor_sync(0xffffffffu, s2, o);
    }
    const float mu = s * (1.f / QKDIM);
    const float var = s2 * (1.f / QKDIM) - mu * mu;
    const float r = rsqrtf(var + LN_EPS);
#pragma unroll
    for (int i = 0; i < 6; ++i) {
        const int c = lane + 32 * i;
        p[c] = (x[i] - mu) * r * gg[c] + bb[c];
    }
}

// ---------------- per-chunk state: S_c = k2_c^T v_c, z_c = sum k2_c ------
// k2 generated on the fly from k. grid = B*H*NC*2 (d halves). M=128(d),N=128(v),K=128(c)
__global__ __launch_bounds__(256) void kvstate_bf16() {
    __shared__ unsigned sAh[16 * SAS], sAl[16 * SAS], sBh[16 * SAS], sBl[16 * SAS];
    __shared__ float ksm[128 * 17];    // k tile (stride 17); reused as zred at end
    const int gx = blockIdx.x;
    const int dhalf = gx & 1;
    const int rest = gx >> 1;
    const int ch = rest & (NC - 1);
    const int bh = rest / NC;
    const int b = bh / HH, h = bh % HH;
    const int d0 = dhalf * 128;

    const int tid = threadIdx.x;
    const int lane = tid & 31, w = tid >> 5;
    const int g = lane >> 2, t = lane & 3;
    const int mbase = (w & 1) * 64, nbase = (w >> 1) * 32;
    const int pc = tid >> 4, eg = (tid & 15) * 8;

    const float* kb = g_k + (size_t)(b * LLEN + ch * CH) * QKDIM + h * FDIM;
    const float* vb = g_v + (size_t)(b * LLEN + ch * CH) * DMODEL + h * DVDIM;

#pragma unroll
    for (int u = 0; u < 2; ++u) {
        const int lin = tid * 2 + u;
        const int r = lin >> 2, c4 = (lin & 3) * 4;
        float4 kv = *(const float4*)(kb + (size_t)r * QKDIM + c4);
        ksm[r * 17 + c4 + 0] = kv.x; ksm[r * 17 + c4 + 1] = kv.y;
        ksm[r * 17 + c4 + 2] = kv.z; ksm[r * 17 + c4 + 3] = kv.w;
    }

    const int iA = (d0 + eg) >> 4;   // constant i for this thread's 8 d's
    const int jb = eg & 15;          // j base (0 or 8)

    float acc[16][4];
#pragma unroll
    for (int i = 0; i < 16; ++i) acc[i][0] = acc[i][1] = acc[i][2] = acc[i][3] = 0.f;
    float zacc[8];
#pragma unroll
    for (int e = 0; e < 8; ++e) zacc[e] = 0.f;

    float vA[8], vB[8];
    {
        const float* r0p = vb + (size_t)(2 * pc) * DMODEL + eg;
        const float* r1p = vb + (size_t)(2 * pc + 1) * DMODEL + eg;
        float4 x0 = *(const float4*)r0p, x1 = *(const float4*)(r0p + 4);
        float4 y0 = *(const float4*)r1p, y1 = *(const float4*)(r1p + 4);
        vA[0]=x0.x; vA[1]=x0.y; vA[2]=x0.z; vA[3]=x0.w; vA[4]=x1.x; vA[5]=x1.y; vA[6]=x1.z; vA[7]=x1.w;
        vB[0]=y0.x; vB[1]=y0.y; vB[2]=y0.z; vB[3]=y0.w; vB[4]=y1.x; vB[5]=y1.y; vB[6]=y1.z; vB[7]=y1.w;
    }
    __syncthreads();

    for (int s = 0; s < 4; ++s) {
        const int ca = s * 32 + 2 * pc, cb2 = ca + 1;
        const float kia = ksm[ca * 17 + iA] * 0.25f;
        const float kib = ksm[cb2 * 17 + iA] * 0.25f;
#pragma unroll
        for (int e = 0; e < 8; ++e) {
            const float pa = kia * ksm[ca * 17 + jb + e];
            const float pb = kib * ksm[cb2 * 17 + jb + e];
            zacc[e] += pa + pb;
            unsigned h_, l_;
            split2(pa, pb, h_, l_);
            sAh[pc * SAS + eg + e] = h_;
            sAl[pc * SAS + eg + e] = l_;
        }
        {
            unsigned hh[8], ll[8];
#pragma unroll
            for (int e = 0; e < 8; ++e) split2(vA[e], vB[e], hh[e], ll[e]);
            *(uint4*)&sBh[pc * SAS + eg]     = make_uint4(hh[0], hh[1], hh[2], hh[3]);
            *(uint4*)&sBh[pc * SAS + eg + 4] = make_uint4(hh[4], hh[5], hh[6], hh[7]);
            *(uint4*)&sBl[pc * SAS + eg]     = make_uint4(ll[0], ll[1], ll[2], ll[3]);
            *(uint4*)&sBl[pc * SAS + eg + 4] = make_uint4(ll[4], ll[5], ll[6], ll[7]);
        }
        __syncthreads();
        if (s + 1 < 4) {
            const int c0 = (s + 1) * 32;
            const float* r0p = vb + (size_t)(c0 + 2 * pc) * DMODEL + eg;
            const float* r1p = vb + (size_t)(c0 + 2 * pc + 1) * DMODEL + eg;
            float4 x0 = *(const float4*)r0p, x1 = *(const float4*)(r0p + 4);
            float4 y0 = *(const float4*)r1p, y1 = *(const float4*)(r1p + 4);
            vA[0]=x0.x; vA[1]=x0.y; vA[2]=x0.z; vA[3]=x0.w; vA[4]=x1.x; vA[5]=x1.y; vA[6]=x1.z; vA[7]=x1.w;
            vB[0]=y0.x; vB[1]=y0.y; vB[2]=y0.z; vB[3]=y0.w; vB[4]=y1.x; vB[5]=y1.y; vB[6]=y1.z; vB[7]=y1.w;
        }
        warp_mma3(sAh, sAl, sBh, sBl, mbase, nbase, g, t, acc);
        __syncthreads();
    }

    float* Sout = g_S + (((size_t)bh * NC + ch) * D2 + d0) * DVDIM;
#pragma unroll
    for (int mt = 0; mt < 4; ++mt) {
        const int r0 = mbase + mt * 16 + g;
#pragma unroll
        for (int nt = 0; nt < 4; ++nt) {
            const int col = nbase + nt * 8 + t * 2;
            const float* a4 = acc[mt * 4 + nt];
            *(float2*)(Sout + (size_t)r0 * DVDIM + col)       = make_float2(a4[0], a4[1]);
            *(float2*)(Sout + (size_t)(r0 + 8) * DVDIM + col) = make_float2(a4[2], a4[3]);
        }
    }
    // z reduction: reuse ksm as zred[16][128]
    __syncthreads();
#pragma unroll
    for (int e = 0; e < 8; ++e) ksm[pc * 128 + eg + e] = zacc[e];
    __syncthreads();
    if (tid < 128) {
        float z = 0.f;
#pragma unroll
        for (int p = 0; p < 16; ++p) z += ksm[p * 128 + tid];
        g_z[((size_t)bh * NC + ch) * D2 + d0 + tid] = z;
    }
}

// ---------------- exclusive prefix over chunks ----------------
__global__ __launch_bounds__(256) void prefix_kernel() {
    const int NS = BB * HH * D2 * DVDIM;
    const int NZ = BB * HH * D2;
    const int idx = blockIdx.x * blockDim.x + threadIdx.x;
    if (idx < NS) {
        const int bh = idx / (D2 * DVDIM);
        const int rem = idx % (D2 * DVDIM);
        const size_t base = (size_t)bh * NC * D2 * DVDIM + rem;
        float run = 0.f;
#pragma unroll
        for (int c = 0; c < NC; ++c) {
            const size_t p = base + (size_t)c * (D2 * DVDIM);
            const float t2 = g_S[p]; g_S[p] = run; run += t2;
        }
    } else if (idx < NS + NZ) {
        const int j = idx - NS;
        const int bh = j / D2, rem = j % D2;
        const size_t base = (size_t)bh * NC * D2 + rem;
        float run = 0.f;
#pragma unroll
        for (int c = 0; c < NC; ++c) {
            const size_t p = base + (size_t)c * D2;
            const float t2 = g_z[p]; g_z[p] = run; run += t2;
        }
    }
}

// ---------------- attention A (fp32 exact): A = mask((q.k)^2/16), den ----
__global__ __launch_bounds__(256) void attn_a_new() {
    __shared__ float qs[128 * 17];
    __shared__ float ksm[128 * 17];
    __shared__ float Zs[256];
    __shared__ float rsum[256];
    const int gx = blockIdx.x;
    const int ch = gx & (NC - 1), bh = gx / NC;
    const int b = bh / HH, h = bh % HH;
    const int tid = threadIdx.x;
    const float* qb = g_q + (size_t)(b * LLEN + ch * CH) * QKDIM + h * FDIM;
    const float* kb = g_k + (size_t)(b * LLEN + ch * CH) * QKDIM + h * FDIM;
#pragma unroll
    for (int u = 0; u < 2; ++u) {
        const int lin = tid * 2 + u;
        const int r = lin >> 2, c4 = (lin & 3) * 4;
        float4 qv = *(const float4*)(qb + (size_t)r * QKDIM + c4);
        qs[r * 17 + c4 + 0] = qv.x; qs[r * 17 + c4 + 1] = qv.y;
        qs[r * 17 + c4 + 2] = qv.z; qs[r * 17 + c4 + 3] = qv.w;
        float4 kv = *(const float4*)(kb + (size_t)r * QKDIM + c4);
        ksm[r * 17 + c4 + 0] = kv.x; ksm[r * 17 + c4 + 1] = kv.y;
        ksm[r * 17 + c4 + 2] = kv.z; ksm[r * 17 + c4 + 3] = kv.w;
    }
    Zs[tid] = g_z[((size_t)bh * NC + ch) * D2 + tid];
    __syncthreads();

    const int r = tid >> 1, cb = (tid & 1) * 64;
    float qr[16];
#pragma unroll
    for (int i = 0; i < 16; ++i) qr[i] = qs[r * 17 + i];
    float rs = 0.f;
    float* Ab = g_A + (size_t)gx * CH * CH + (size_t)r * CH + cb;
    for (int cc = 0; cc < 64; cc += 4) {
        float4 av;
        float* ap = (float*)&av;
#pragma unroll
        for (int e = 0; e < 4; ++e) {
            const int c = cb + cc + e;
            float sd = 0.f;
#pragma unroll
            for (int i = 0; i < 16; ++i) sd = fmaf(qr[i], ksm[c * 17 + i], sd);
            const float a = (c <= r) ? sd * sd * 0.0625f : 0.f;
            ap[e] = a; rs += a;
        }
        *(float4*)(Ab + cc) = av;
    }
    rsum[tid] = rs;
    __syncthreads();
    if (tid < 128) {
        float den = 0.f;
#pragma unroll
        for (int i = 0; i < 16; ++i) {
            float y = 0.f;
#pragma unroll
            for (int j = 0; j < 16; ++j) y = fmaf(Zs[i * 16 + j], qs[tid * 17 + j], y);
            den = fmaf(qs[tid * 17 + i], y, den);
        }
        g_den[(size_t)gx * CH + tid] = den * 0.25f + rsum[2 * tid] + rsum[2 * tid + 1];
    }
}

// ---------------- attention B: o = (q2 S + A v) / (den + eps) ----------
__global__ __launch_bounds__(256) void attn_b_bf16() {
    __shared__ unsigned sAh[16 * SAS], sAl[16 * SAS], sBh[16 * SAS], sBl[16 * SAS];
    __shared__ float qsm[128 * 17];
    __shared__ float dens[CH];
    const int gx = blockIdx.x;
    const int ch = gx & (NC - 1), bh = gx / NC;
    const int b = bh / HH, h = bh % HH;
    const int tid = threadIdx.x;
    const int lane = tid & 31, w = tid >> 5;
    const int g = lane >> 2, t = lane & 3;
    const int mbase = (w & 1) * 64, nbase = (w >> 1) * 32;
    const int arow = tid >> 1, akc = (tid & 1) * 4;
    const int pkr = tid >> 4, bn = (tid & 15) * 8;

    const float* qb = g_q + (size_t)(b * LLEN + ch * CH) * QKDIM + h * FDIM;
    const float* Sb = g_S + ((size_t)bh * NC + ch) * D2 * DVDIM;
    const float* Abp = g_A + (size_t)gx * CH * CH;
    const float* vb = g_v + (size_t)(b * LLEN + ch * CH) * DMODEL + h * DVDIM;

#pragma unroll
    for (int u = 0; u < 2; ++u) {
        const int lin = tid * 2 + u;
        const int r = lin >> 2, c4 = (lin & 3) * 4;
        float4 qv = *(const float4*)(qb + (size_t)r * QKDIM + c4);
        qsm[r * 17 + c4 + 0] = qv.x; qsm[r * 17 + c4 + 1] = qv.y;
        qsm[r * 17 + c4 + 2] = qv.z; qsm[r * 17 + c4 + 3] = qv.w;
    }
    if (tid < CH) dens[tid] = g_den[(size_t)gx * CH + tid];

    float acc[16][4];
#pragma unroll
    for (int i = 0; i < 16; ++i) acc[i][0] = acc[i][1] = acc[i][2] = acc[i][3] = 0.f;

    float bA[8], bB[8];
    {
        const float* r0p = Sb + (size_t)(2 * pkr) * DVDIM + bn;
        const float* r1p = Sb + (size_t)(2 * pkr + 1) * DVDIM + bn;
        float4 x0 = *(const float4*)r0p, x1 = *(const float4*)(r0p + 4);
        float4 y0 = *(const float4*)r1p, y1 = *(const float4*)(r1p + 4);
        bA[0]=x0.x; bA[1]=x0.y; bA[2]=x0.z; bA[3]=x0.w; bA[4]=x1.x; bA[5]=x1.y; bA[6]=x1.z; bA[7]=x1.w;
        bB[0]=y0.x; bB[1]=y0.y; bB[2]=y0.z; bB[3]=y0.w; bB[4]=y1.x; bB[5]=y1.y; bB[6]=y1.z; bB[7]=y1.w;
    }

    // phase 1: q2 (on the fly) @ S, K = 256
    for (int s = 0; s < 8; ++s) {
        __syncthreads();
#pragma unroll
        for (int u = 0; u < 4; ++u) {
            const int dbase = s * 32 + akc + 8 * u;
            const int ii = dbase >> 4, j0 = dbase & 15;
            const float qi = qsm[arow * 17 + ii] * 0.25f;
            const float p0 = qi * qsm[arow * 17 + j0];
            const float p1 = qi * qsm[arow * 17 + j0 + 1];
            const float p2 = qi * qsm[arow * 17 + j0 + 2];
            const float p3 = qi * qsm[arow * 17 + j0 + 3];
            const int kp = (tid & 1) * 2 + 4 * u;
            unsigned h0, l0, h1, l1;
            split2(p0, p1, h0, l0);
            split2(p2, p3, h1, l1);
            sAh[kp * SAS + arow] = h0;       sAl[kp * SAS + arow] = l0;
            sAh[(kp + 1) * SAS + arow] = h1; sAl[(kp + 1) * SAS + arow] = l1;
        }
        {
            unsigned hh[8], ll[8];
#pragma unroll
            for (int e = 0; e < 8; ++e) split2(bA[e], bB[e], hh[e], ll[e]);
            *(uint4*)&sBh[pkr * SAS + bn]     = make_uint4(hh[0], hh[1], hh[2], hh[3]);
            *(uint4*)&sBh[pkr * SAS + bn + 4] = make_uint4(hh[4], hh[5], hh[6], hh[7]);
            *(uint4*)&sBl[pkr * SAS + bn]     = make_uint4(ll[0], ll[1], ll[2], ll[3]);
            *(uint4*)&sBl[pkr * SAS + bn + 4] = make_uint4(ll[4], ll[5], ll[6], ll[7]);
        }
        __syncthreads();
        if (s + 1 < 8) {
            const int d1 = (s + 1) * 32;
            const float* r0p = Sb + (size_t)(d1 + 2 * pkr) * DVDIM + bn;
            const float* r1p = Sb + (size_t)(d1 + 2 * pkr + 1) * DVDIM + bn;
            float4 x0 = *(const float4*)r0p, x1 = *(const float4*)(r0p + 4);
            float4 y0 = *(const float4*)r1p, y1 = *(const float4*)(r1p + 4);
            bA[0]=x0.x; bA[1]=x0.y; bA[2]=x0.z; bA[3]=x0.w; bA[4]=x1.x; bA[5]=x1.y; bA[6]=x1.z; bA[7]=x1.w;
            bB[0]=y0.x; bB[1]=y0.y; bB[2]=y0.z; bB[3]=y0.w; bB[4]=y1.x; bB[5]=y1.y; bB[6]=y1.z; bB[7]=y1.w;
        }
        warp_mma3(sAh, sAl, sBh, sBl, mbase, nbase, g, t, acc);
    }

    // phase 2: A @ v, K = 128
    float4 raf[4];
#pragma unroll
    for (int u = 0; u < 4; ++u)
        raf[u] = *(const float4*)(Abp + (size_t)arow * CH + akc + 8 * u);
    {
        const float* r0p = vb + (size_t)(2 * pkr) * DMODEL + bn;
        const float* r1p = vb + (size_t)(2 * pkr + 1) * DMODEL + bn;
        float4 x0 = *(const float4*)r0p, x1 = *(const float4*)(r0p + 4);
        float4 y0 = *(const float4*)r1p, y1 = *(const float4*)(r1p + 4);
        bA[0]=x0.x; bA[1]=x0.y; bA[2]=x0.z; bA[3]=x0.w; bA[4]=x1.x; bA[5]=x1.y; bA[6]=x1.z; bA[7]=x1.w;
        bB[0]=y0.x; bB[1]=y0.y; bB[2]=y0.z; bB[3]=y0.w; bB[4]=y1.x; bB[5]=y1.y; bB[6]=y1.z; bB[7]=y1.w;
    }
    for (int s = 0; s < 4; ++s) {
        __syncthreads();
#pragma unroll
        for (int u = 0; u < 4; ++u) {
            const int kp = (tid & 1) * 2 + 4 * u;
            unsigned h0, l0, h1, l1;
            split2(raf[u].x, raf[u].y, h0, l0);
            split2(raf[u].z, raf[u].w, h1, l1);
            sAh[kp * SAS + arow] = h0;       sAl[kp * SAS + arow] = l0;
            sAh[(kp + 1) * SAS + arow] = h1; sAl[(kp + 1) * SAS + arow] = l1;
        }
        {
            unsigned hh[8], ll[8];
#pragma unroll
            for (int e = 0; e < 8; ++e) split2(bA[e], bB[e], hh[e], ll[e]);
            *(uint4*)&sBh[pkr * SAS + bn]     = make_uint4(hh[0], hh[1], hh[2], hh[3]);
            *(uint4*)&sBh[pkr * SAS + bn + 4] = make_uint4(hh[4], hh[5], hh[6], hh[7]);
            *(uint4*)&sBl[pkr * SAS + bn]     = make_uint4(ll[0], ll[1], ll[2], ll[3]);
            *(uint4*)&sBl[pkr * SAS + bn + 4] = make_uint4(ll[4], ll[5], ll[6], ll[7]);
        }
        __syncthreads();
        if (s + 1 < 4) {
            const int c0 = (s + 1) * 32;
#pragma unroll
            for (int u = 0; u < 4; ++u)
                raf[u] = *(const float4*)(Abp + (size_t)arow * CH + c0 + akc + 8 * u);
            const float* r0p = vb + (size_t)(c0 + 2 * pkr) * DMODEL + bn;
            const float* r1p = vb + (size_t)(c0 + 2 * pkr + 1) * DMODEL + bn;
            float4 x0 = *(const float4*)r0p, x1 = *(const float4*)(r0p + 4);
            float4 y0 = *(const float4*)r1p, y1 = *(const float4*)(r1p + 4);
            bA[0]=x0.x; bA[1]=x0.y; bA[2]=x0.z; bA[3]=x0.w; bA[4]=x1.x; bA[5]=x1.y; bA[6]=x1.z; bA[7]=x1.w;
            bB[0]=y0.x; bB[1]=y0.y; bB[2]=y0.z; bB[3]=y0.w; bB[4]=y1.x; bB[5]=y1.y; bB[6]=y1.z; bB[7]=y1.w;
        }
        warp_mma3(sAh, sAl, sBh, sBl, mbase, nbase, g, t, acc);
    }

    float* ob = g_oh + (size_t)(b * LLEN + ch * CH) * DMODEL + h * DVDIM;
#pragma unroll
    for (int mt = 0; mt < 4; ++mt) {
        const int r0 = mbase + mt * 16 + g;
        const float inv0 = 1.f / (dens[r0] + EPS);
        const float inv1 = 1.f / (dens[r0 + 8] + EPS);
#pragma unroll
        for (int nt = 0; nt < 4; ++nt) {
            const int col = nbase + nt * 8 + t * 2;
            const float* a4 = acc[mt * 4 + nt];
            *(float2*)(ob + (size_t)r0 * DMODEL + col)       = make_float2(a4[0] * inv0, a4[1] * inv0);
            *(float2*)(ob + (size_t)(r0 + 8) * DMODEL + col) = make_float2(a4[2] * inv1, a4[3] * inv1);
        }
    }
}

// ---------------- host pipeline ----------------
extern "C" void kernel_launch(void* const* d_in, const int* in_sizes, int n_in,
                              void* d_out, int out_size) {
    (void)in_sizes; (void)n_in; (void)out_size;
    const float* x   = (const float*)d_in[0];
    const float* Wq  = (const float*)d_in[1];
    const float* Wk  = (const float*)d_in[2];
    const float* Wv  = (const float*)d_in[3];
    const float* Wo  = (const float*)d_in[4];
    const float* lqg = (const float*)d_in[5];
    const float* lqb = (const float*)d_in[6];
    const float* lkg = (const float*)d_in[7];
    const float* lkb = (const float*)d_in[8];
    float* out = (float*)d_out;

    float *vp, *ohp;
    cudaGetSymbolAddress((void**)&vp, g_v);
    cudaGetSymbolAddress((void**)&ohp, g_oh);

    projqk_kernel<<<dim3(2, 32, 2), 256>>>(x, Wq, Wk);
    proj_kernel<<<dim3(12, 32), 256>>>(x, Wv, vp, DMODEL, DMODEL);
    ln_kernel<<<(2 * NTOK) / 8, 256>>>(lqg, lqb, lkg, lkb);
    kvstate_bf16<<<BB * HH * NC * 2, 256>>>();
    {
        const int total = BB * HH * D2 * DVDIM + BB * HH * D2;
        prefix_kernel<<<(total + 255) / 256, 256>>>();
    }
    attn_a_new<<<BB * HH * NC, 256>>>();
    attn_b_bf16<<<BB * HH * NC, 256>>>();
    proj_kernel<<<dim3(12, 32), 256>>>(ohp, Wo, out, DMODEL, DMODEL);
}

// round 4
// speedup vs baseline: 3.6590x; 1.1264x over previous
#include <cuda_runtime.h>
#include <cuda_bf16.h>

// ---------------- problem constants ----------------
#define BB     2
#define LLEN   2048
#define DMODEL 1536
#define HH     12
#define FDIM   16
#define DVDIM  128
#define D2     256
#define CH     128
#define NC     16
#define NTOK   4096
#define QKDIM  192
#define LN_EPS 1e-5f
#define EPS    1e-12f
#define MKS    40    // MK tile: [m up to 128][k 32] bf16, k-stride 40 (80B rows)
#define KNS    136   // KN tile: [k 32][n 128] bf16, n-stride 136 (272B rows)

// ---------------- scratch (device globals) ----------------
__device__ float g_q [NTOK * QKDIM];
__device__ float g_k [NTOK * QKDIM];
__device__ float g_v [(size_t)NTOK * DMODEL];
__device__ float g_S [(size_t)BB * HH * NC * D2 * DVDIM];
__device__ float g_z [(size_t)BB * HH * NC * D2];
__device__ float g_A [(size_t)BB * HH * NC * CH * CH];
__device__ float g_den[(size_t)BB * HH * NC * CH];
__device__ float g_oh[(size_t)NTOK * DMODEL];

// ---------------- helpers ----------------
__device__ __forceinline__ unsigned sptr(const void* p) {
    return (unsigned)__cvta_generic_to_shared(p);
}
// (x,y) -> hi bf16x2 (x in low 16), residual lo bf16x2
__device__ __forceinline__ void split2(float x, float y, unsigned& h, unsigned& l) {
    __nv_bfloat162 hh = __floats2bfloat162_rn(x, y);
    float rx = x - __low2float(hh);
    float ry = y - __high2float(hh);
    __nv_bfloat162 ll = __floats2bfloat162_rn(rx, ry);
    h = *reinterpret_cast<unsigned*>(&hh);
    l = *reinterpret_cast<unsigned*>(&ll);
}
// 8 consecutive floats -> 16B hi + 16B lo
__device__ __forceinline__ void split8(const float* v, uint4& h, uint4& l) {
    split2(v[0], v[1], h.x, l.x);
    split2(v[2], v[3], h.y, l.y);
    split2(v[4], v[5], h.z, l.z);
    split2(v[6], v[7], h.w, l.w);
}
__device__ __forceinline__ void mma16(float* c, const unsigned* a, const unsigned* b) {
    asm volatile("mma.sync.aligned.m16n8k16.row.col.f32.bf16.bf16.f32 "
        "{%0,%1,%2,%3},{%4,%5,%6,%7},{%8,%9},{%0,%1,%2,%3};"
        : "+f"(c[0]), "+f"(c[1]), "+f"(c[2]), "+f"(c[3])
        : "r"(a[0]), "r"(a[1]), "r"(a[2]), "r"(a[3]), "r"(b[0]), "r"(b[1]));
}
__device__ __forceinline__ void ldsm4(uint4& r, unsigned a) {
    asm volatile("ldmatrix.sync.aligned.m8n8.x4.shared.b16 {%0,%1,%2,%3},[%4];"
        : "=r"(r.x), "=r"(r.y), "=r"(r.z), "=r"(r.w) : "r"(a));
}
__device__ __forceinline__ void ldsm4t(uint4& r, unsigned a) {
    asm volatile("ldmatrix.sync.aligned.m8n8.x4.trans.shared.b16 {%0,%1,%2,%3},[%4];"
        : "=r"(r.x), "=r"(r.y), "=r"(r.z), "=r"(r.w) : "r"(a));
}
// 3-term tile update: Ah*Bh + Al*Bh + Ah*Bl
__device__ __forceinline__ void tile3(float* acc, const uint4& ah, const uint4& al,
                                      unsigned bh0, unsigned bh1, unsigned bl0, unsigned bl1) {
    unsigned A[4] = {ah.x, ah.y, ah.z, ah.w};
    unsigned L[4] = {al.x, al.y, al.z, al.w};
    unsigned BH[2] = {bh0, bh1}, BL[2] = {bl0, bl1};
    mma16(acc, A, BH);
    mma16(acc, L, BH);
    mma16(acc, A, BL);
}

// One BK=32 stage via ldmatrix. ATR=false: A from MK (no-trans); true: A from KN (.trans).
// B always from KN via .trans. Addresses are lane-resolved byte addrs in shared space.
template<bool ATR>
__device__ __forceinline__ void mma_stage(unsigned fAh, unsigned fAl,
                                          unsigned fBh, unsigned fBl,
                                          float (*acc)[4]) {
    const int aMT = ATR ? 32 : 1280;     // per-mt (16 m): 16 cols vs 16 rows*80B
    const int aO  = ATR ? 4352 : 32;     // per-o (16 k): 16 rows*272B vs 16 cols*2B
#pragma unroll
    for (int o = 0; o < 2; ++o) {
        uint4 ah[4], al[4], bh[2], bl[2];
#pragma unroll
        for (int mt = 0; mt < 4; ++mt) {
            if (ATR) { ldsm4t(ah[mt], fAh + o * aO + mt * aMT); ldsm4t(al[mt], fAl + o * aO + mt * aMT); }
            else     { ldsm4 (ah[mt], fAh + o * aO + mt * aMT); ldsm4 (al[mt], fAl + o * aO + mt * aMT); }
        }
#pragma unroll
        for (int p = 0; p < 2; ++p) {
            ldsm4t(bh[p], fBh + o * 4352 + p * 32);
            ldsm4t(bl[p], fBl + o * 4352 + p * 32);
        }
#pragma unroll
        for (int mt = 0; mt < 4; ++mt)
#pragma unroll
            for (int p = 0; p < 2; ++p) {
                tile3(acc[mt * 4 + 2 * p],     ah[mt], al[mt], bh[p].x, bh[p].y, bl[p].x, bl[p].y);
                tile3(acc[mt * 4 + 2 * p + 1], ah[mt], al[mt], bh[p].z, bh[p].w, bl[p].z, bl[p].w);
            }
    }
}

// ---------------- generic projection GEMM core ----------------
__device__ __forceinline__ void gemm_core(const float* __restrict__ A,
                                          const float* __restrict__ B,
                                          float* __restrict__ C,
                                          int N, int K, int m0, int n0,
                                          __nv_bfloat16* sAh, __nv_bfloat16* sAl,
                                          __nv_bfloat16* sBh, __nv_bfloat16* sBl) {
    const int tid = threadIdx.x, lane = tid & 31, w = tid >> 5;
    const int g = lane >> 2, t = lane & 3;
    const int mbase = (w & 1) * 64, nbase = (w >> 1) * 32;
    const int arow = tid >> 1, kseg = (tid & 1) * 16;
    const int krow = tid >> 3, nseg = (tid & 7) * 16;
    const bool bval = (n0 + nseg) < N;

    const unsigned offA = ((mbase + (lane & 15)) * MKS + (lane >> 4) * 8) * 2;
    const unsigned fAh = sptr(sAh) + offA;
    const unsigned fAl = sptr(sAl) + offA;
    const unsigned offB = ((((lane >> 3) & 1) * 8 + (lane & 7)) * KNS + nbase + ((lane >> 4) & 1) * 8) * 2;
    const unsigned fBh = sptr(sBh) + offB;
    const unsigned fBl = sptr(sBl) + offB;

    uint4* stAh = (uint4*)(sAh + arow * MKS + kseg);
    uint4* stAl = (uint4*)(sAl + arow * MKS + kseg);
    uint4* stBh = (uint4*)(sBh + krow * KNS + nseg);
    uint4* stBl = (uint4*)(sBl + krow * KNS + nseg);

    float acc[16][4];
#pragma unroll
    for (int i = 0; i < 16; ++i) acc[i][0] = acc[i][1] = acc[i][2] = acc[i][3] = 0.f;

    float4 ra[4], rb[4];
#pragma unroll
    for (int i = 0; i < 4; ++i) {
        ra[i] = *(const float4*)(A + (size_t)(m0 + arow) * K + kseg + 4 * i);
        rb[i] = bval ? *(const float4*)(B + (size_t)krow * N + n0 + nseg + 4 * i)
                     : make_float4(0.f, 0.f, 0.f, 0.f);
    }
    const int NSt = K >> 5;
    for (int s = 0; s < NSt; ++s) {
        __syncthreads();
        {
            uint4 h4, l4;
            split8((const float*)&ra[0], h4, l4); stAh[0] = h4; stAl[0] = l4;
            split8((const float*)&ra[2], h4, l4); stAh[1] = h4; stAl[1] = l4;
            split8((const float*)&rb[0], h4, l4); stBh[0] = h4; stBl[0] = l4;
            split8((const float*)&rb[2], h4, l4); stBh[1] = h4; stBl[1] = l4;
        }
        __syncthreads();
        if (s + 1 < NSt) {
            const int k0 = (s + 1) * 32;
#pragma unroll
            for (int i = 0; i < 4; ++i) {
                ra[i] = *(const float4*)(A + (size_t)(m0 + arow) * K + k0 + kseg + 4 * i);
                rb[i] = bval ? *(const float4*)(B + (size_t)(k0 + krow) * N + n0 + nseg + 4 * i)
                             : make_float4(0.f, 0.f, 0.f, 0.f);
            }
        }
        mma_stage<false>(fAh, fAl, fBh, fBl, acc);
    }
#pragma unroll
    for (int mt = 0; mt < 4; ++mt) {
        const int r0 = m0 + mbase + mt * 16 + g;
#pragma unroll
        for (int nt = 0; nt < 4; ++nt) {
            const int col = n0 + nbase + nt * 8 + t * 2;
            if (col < N) {
                const float* a4 = acc[mt * 4 + nt];
                *(float2*)(C + (size_t)r0 * N + col)       = make_float2(a4[0], a4[1]);
                *(float2*)(C + (size_t)(r0 + 8) * N + col) = make_float2(a4[2], a4[3]);
            }
        }
    }
}

__global__ __launch_bounds__(256) void projqk_kernel(const float* __restrict__ x,
                                                     const float* __restrict__ Wq,
                                                     const float* __restrict__ Wk) {
    __shared__ __align__(16) __nv_bfloat16 sAh[128 * MKS], sAl[128 * MKS];
    __shared__ __align__(16) __nv_bfloat16 sBh[32 * KNS],  sBl[32 * KNS];
    const float* B = blockIdx.z ? Wk : Wq;
    float* C = blockIdx.z ? (float*)g_k : (float*)g_q;
    gemm_core(x, B, C, QKDIM, DMODEL, blockIdx.y * 128, blockIdx.x * 128, sAh, sAl, sBh, sBl);
}

__global__ __launch_bounds__(256) void proj_kernel(const float* __restrict__ A,
                                                   const float* __restrict__ B,
                                                   float* __restrict__ C, int N, int K) {
    __shared__ __align__(16) __nv_bfloat16 sAh[128 * MKS], sAl[128 * MKS];
    __shared__ __align__(16) __nv_bfloat16 sBh[32 * KNS],  sBl[32 * KNS];
    gemm_core(A, B, C, N, K, blockIdx.y * 128, blockIdx.x * 128, sAh, sAl, sBh, sBl);
}

// ---------------- LayerNorm over 192 dims, in place ----------------
__global__ __launch_bounds__(256) void ln_kernel(const float* __restrict__ gq,
                                                 const float* __restrict__ bq,
                                                 const float* __restrict__ gk,
                                                 const float* __restrict__ bk) {
    const int warp = (blockIdx.x * blockDim.x + threadIdx.x) >> 5;
    const int lane = threadIdx.x & 31;
    if (warp >= 2 * NTOK) return;
    const bool isq = warp < NTOK;
    float* p = isq ? (g_q + (size_t)warp * QKDIM) : (g_k + (size_t)(warp - NTOK) * QKDIM);
    const float* gg = isq ? gq : gk;
    const float* bb = isq ? bq : bk;
    float x[6]; float s = 0.f, s2 = 0.f;
#pragma unroll
    for (int i = 0; i < 6; ++i) { x[i] = p[lane + 32 * i]; s += x[i]; s2 = fmaf(x[i], x[i], s2); }
#pragma unroll
    for (int o = 16; o > 0; o >>= 1) {
        s += __shfl_xor_sync(0xffffffffu, s, o);
        s2 += __shfl_xor_sync(0xffffffffu, s2, o);
    }
    const float mu = s * (1.f / QKDIM);
    const float var = s2 * (1.f / QKDIM) - mu * mu;
    const float r = rsqrtf(var + LN_EPS);
#pragma unroll
    for (int i = 0; i < 6; ++i) {
        const int c = lane + 32 * i;
        p[c] = (x[i] - mu) * r * gg[c] + bb[c];
    }
}

// ---------------- per-chunk state: S_c = k2_c^T v_c, z_c = sum k2_c ------
__global__ __launch_bounds__(256) void kvstate_bf16() {
    __shared__ __align__(16) __nv_bfloat16 sAh[32 * KNS], sAl[32 * KNS];
    __shared__ __align__(16) __nv_bfloat16 sBh[32 * KNS], sBl[32 * KNS];
    __shared__ float ksm[128 * 17];
    const int gx = blockIdx.x;
    const int dhalf = gx & 1, rest = gx >> 1;
    const int ch = rest & (NC - 1), bh = rest / NC;
    const int b = bh / HH, h = bh % HH;
    const int d0 = dhalf * 128;
    const int tid = threadIdx.x, lane = tid & 31, w = tid >> 5;
    const int g = lane >> 2, t = lane & 3;
    const int mbase = (w & 1) * 64, nbase = (w >> 1) * 32;
    const int pc = tid >> 4, eg = (tid & 15) * 8;

    const float* kb = g_k + (size_t)(b * LLEN + ch * CH) * QKDIM + h * FDIM;
    const float* vb = g_v + (size_t)(b * LLEN + ch * CH) * DMODEL + h * DVDIM;

#pragma unroll
    for (int u = 0; u < 2; ++u) {
        const int lin = tid * 2 + u;
        const int r = lin >> 2, c4 = (lin & 3) * 4;
        float4 kv = *(const float4*)(kb + (size_t)r * QKDIM + c4);
        ksm[r * 17 + c4 + 0] = kv.x; ksm[r * 17 + c4 + 1] = kv.y;
        ksm[r * 17 + c4 + 2] = kv.z; ksm[r * 17 + c4 + 3] = kv.w;
    }

    const int iA = (d0 + eg) >> 4;
    const int jb = eg & 15;

    const unsigned offA = ((((lane >> 4) & 1) * 8 + (lane & 7)) * KNS + mbase + ((lane >> 3) & 1) * 8) * 2;
    const unsigned fAh = sptr(sAh) + offA;
    const unsigned fAl = sptr(sAl) + offA;
    const unsigned offB = ((((lane >> 3) & 1) * 8 + (lane & 7)) * KNS + nbase + ((lane >> 4) & 1) * 8) * 2;
    const unsigned fBh = sptr(sBh) + offB;
    const unsigned fBl = sptr(sBl) + offB;

    uint4* stAh0 = (uint4*)(sAh + (2 * pc) * KNS + eg);
    uint4* stAl0 = (uint4*)(sAl + (2 * pc) * KNS + eg);
    uint4* stAh1 = (uint4*)(sAh + (2 * pc + 1) * KNS + eg);
    uint4* stAl1 = (uint4*)(sAl + (2 * pc + 1) * KNS + eg);
    uint4* stBh0 = (uint4*)(sBh + (2 * pc) * KNS + eg);
    uint4* stBl0 = (uint4*)(sBl + (2 * pc) * KNS + eg);
    uint4* stBh1 = (uint4*)(sBh + (2 * pc + 1) * KNS + eg);
    uint4* stBl1 = (uint4*)(sBl + (2 * pc + 1) * KNS + eg);

    float acc[16][4];
#pragma unroll
    for (int i = 0; i < 16; ++i) acc[i][0] = acc[i][1] = acc[i][2] = acc[i][3] = 0.f;
    float zacc[8];
#pragma unroll
    for (int e = 0; e < 8; ++e) zacc[e] = 0.f;

    float vA[8], vB[8];
    {
        const float* r0p = vb + (size_t)(2 * pc) * DMODEL + eg;
        const float* r1p = vb + (size_t)(2 * pc + 1) * DMODEL + eg;
        *(float4*)&vA[0] = *(const float4*)r0p; *(float4*)&vA[4] = *(const float4*)(r0p + 4);
        *(float4*)&vB[0] = *(const float4*)r1p; *(float4*)&vB[4] = *(const float4*)(r1p + 4);
    }
    __syncthreads();

    for (int s = 0; s < 4; ++s) {
        const int ca = s * 32 + 2 * pc, cb2 = ca + 1;
        float pa[8], pb[8];
        const float kia = ksm[ca * 17 + iA] * 0.25f;
        const float kib = ksm[cb2 * 17 + iA] * 0.25f;
#pragma unroll
        for (int e = 0; e < 8; ++e) {
            pa[e] = kia * ksm[ca * 17 + jb + e];
            pb[e] = kib * ksm[cb2 * 17 + jb + e];
            zacc[e] += pa[e] + pb[e];
        }
        uint4 h4, l4;
        split8(pa, h4, l4); *stAh0 = h4; *stAl0 = l4;
        split8(pb, h4, l4); *stAh1 = h4; *stAl1 = l4;
        split8(vA, h4, l4); *stBh0 = h4; *stBl0 = l4;
        split8(vB, h4, l4); *stBh1 = h4; *stBl1 = l4;
        __syncthreads();
        if (s + 1 < 4) {
            const int c0 = (s + 1) * 32;
            const float* r0p = vb + (size_t)(c0 + 2 * pc) * DMODEL + eg;
            const float* r1p = vb + (size_t)(c0 + 2 * pc + 1) * DMODEL + eg;
            *(float4*)&vA[0] = *(const float4*)r0p; *(float4*)&vA[4] = *(const float4*)(r0p + 4);
            *(float4*)&vB[0] = *(const float4*)r1p; *(float4*)&vB[4] = *(const float4*)(r1p + 4);
        }
        mma_stage<true>(fAh, fAl, fBh, fBl, acc);
        __syncthreads();
    }

    float* Sout = g_S + (((size_t)bh * NC + ch) * D2 + d0) * DVDIM;
#pragma unroll
    for (int mt = 0; mt < 4; ++mt) {
        const int r0 = mbase + mt * 16 + g;
#pragma unroll
        for (int nt = 0; nt < 4; ++nt) {
            const int col = nbase + nt * 8 + t * 2;
            const float* a4 = acc[mt * 4 + nt];
            *(float2*)(Sout + (size_t)r0 * DVDIM + col)       = make_float2(a4[0], a4[1]);
            *(float2*)(Sout + (size_t)(r0 + 8) * DVDIM + col) = make_float2(a4[2], a4[3]);
        }
    }
    // z reduction: reuse ksm as zred[16][128]
#pragma unroll
    for (int e = 0; e < 8; ++e) ksm[pc * 128 + eg + e] = zacc[e];
    __syncthreads();
    if (tid < 128) {
        float z = 0.f;
#pragma unroll
        for (int p = 0; p < 16; ++p) z += ksm[p * 128 + tid];
        g_z[((size_t)bh * NC + ch) * D2 + d0 + tid] = z;
    }
}

// ---------------- exclusive prefix over chunks ----------------
__global__ __launch_bounds__(256) void prefix_kernel() {
    const int NS = BB * HH * D2 * DVDIM;
    const int NZ = BB * HH * D2;
    const int idx = blockIdx.x * blockDim.x + threadIdx.x;
    if (idx < NS) {
        const int bh = idx / (D2 * DVDIM);
        const int rem = idx % (D2 * DVDIM);
        const size_t base = (size_t)bh * NC * D2 * DVDIM + rem;
        float run = 0.f;
#pragma unroll
        for (int c = 0; c < NC; ++c) {
            const size_t p = base + (size_t)c * (D2 * DVDIM);
            const float t2 = g_S[p]; g_S[p] = run; run += t2;
        }
    } else if (idx < NS + NZ) {
        const int j = idx - NS;
        const int bh = j / D2, rem = j % D2;
        const size_t base = (size_t)bh * NC * D2 + rem;
        float run = 0.f;
#pragma unroll
        for (int c = 0; c < NC; ++c) {
            const size_t p = base + (size_t)c * D2;
            const float t2 = g_z[p]; g_z[p] = run; run += t2;
        }
    }
}

// ---------------- attention A (fp32 exact): A = mask((q.k)^2/16), den ----
__global__ __launch_bounds__(256) void attn_a_new() {
    __shared__ float qs[128 * 17];
    __shared__ float ksm[128 * 17];
    __shared__ float Zs[256];
    __shared__ float rsum[256];
    const int gx = blockIdx.x;
    const int ch = gx & (NC - 1), bh = gx / NC;
    const int b = bh / HH, h = bh % HH;
    const int tid = threadIdx.x;
    const float* qb = g_q + (size_t)(b * LLEN + ch * CH) * QKDIM + h * FDIM;
    const float* kb = g_k + (size_t)(b * LLEN + ch * CH) * QKDIM + h * FDIM;
#pragma unroll
    for (int u = 0; u < 2; ++u) {
        const int lin = tid * 2 + u;
        const int r = lin >> 2, c4 = (lin & 3) * 4;
        float4 qv = *(const float4*)(qb + (size_t)r * QKDIM + c4);
        qs[r * 17 + c4 + 0] = qv.x; qs[r * 17 + c4 + 1] = qv.y;
        qs[r * 17 + c4 + 2] = qv.z; qs[r * 17 + c4 + 3] = qv.w;
        float4 kv = *(const float4*)(kb + (size_t)r * QKDIM + c4);
        ksm[r * 17 + c4 + 0] = kv.x; ksm[r * 17 + c4 + 1] = kv.y;
        ksm[r * 17 + c4 + 2] = kv.z; ksm[r * 17 + c4 + 3] = kv.w;
    }
    Zs[tid] = g_z[((size_t)bh * NC + ch) * D2 + tid];
    __syncthreads();

    const int r = tid >> 1, cb = (tid & 1) * 64;
    float qr[16];
#pragma unroll
    for (int i = 0; i < 16; ++i) qr[i] = qs[r * 17 + i];
    float rs = 0.f;
    float* Ab = g_A + (size_t)gx * CH * CH + (size_t)r * CH + cb;
    for (int cc = 0; cc < 64; cc += 4) {
        float4 av;
        float* ap = (float*)&av;
#pragma unroll
        for (int e = 0; e < 4; ++e) {
            const int c = cb + cc + e;
            float sd = 0.f;
#pragma unroll
            for (int i = 0; i < 16; ++i) sd = fmaf(qr[i], ksm[c * 17 + i], sd);
            const float a = (c <= r) ? sd * sd * 0.0625f : 0.f;
            ap[e] = a; rs += a;
        }
        *(float4*)(Ab + cc) = av;
    }
    rsum[tid] = rs;
    __syncthreads();
    if (tid < 128) {
        float den = 0.f;
#pragma unroll
        for (int i = 0; i < 16; ++i) {
            float y = 0.f;
#pragma unroll
            for (int j = 0; j < 16; ++j) y = fmaf(Zs[i * 16 + j], qs[tid * 17 + j], y);
            den = fmaf(qs[tid * 17 + i], y, den);
        }
        g_den[(size_t)gx * CH + tid] = den * 0.25f + rsum[2 * tid] + rsum[2 * tid + 1];
    }
}

// ---------------- attention B: o = (q2 S + A v) / (den + eps) ----------
__global__ __launch_bounds__(256) void attn_b_bf16() {
    __shared__ __align__(16) __nv_bfloat16 sAh[128 * MKS], sAl[128 * MKS];
    __shared__ __align__(16) __nv_bfloat16 sBh[32 * KNS],  sBl[32 * KNS];
    __shared__ float qsm[128 * 17];
    __shared__ float dens[CH];
    const int gx = blockIdx.x;
    const int ch = gx & (NC - 1), bh = gx / NC;
    const int b = bh / HH, h = bh % HH;
    const int tid = threadIdx.x, lane = tid & 31, w = tid >> 5;
    const int g = lane >> 2, t = lane & 3;
    const int mbase = (w & 1) * 64, nbase = (w >> 1) * 32;
    const int arow = tid >> 1, kseg = (tid & 1) * 16;
    const int pkr = tid >> 4, bn = (tid & 15) * 8;

    const float* qb  = g_q + (size_t)(b * LLEN + ch * CH) * QKDIM + h * FDIM;
    const float* Sb  = g_S + ((size_t)bh * NC + ch) * D2 * DVDIM;
    const float* Abp = g_A + (size_t)gx * CH * CH;
    const float* vb  = g_v + (size_t)(b * LLEN + ch * CH) * DMODEL + h * DVDIM;

#pragma unroll
    for (int u = 0; u < 2; ++u) {
        const int lin = tid * 2 + u;
        const int r = lin >> 2, c4 = (lin & 3) * 4;
        float4 qv = *(const float4*)(qb + (size_t)r * QKDIM + c4);
        qsm[r * 17 + c4 + 0] = qv.x; qsm[r * 17 + c4 + 1] = qv.y;
        qsm[r * 17 + c4 + 2] = qv.z; qsm[r * 17 + c4 + 3] = qv.w;
    }
    if (tid < CH) dens[tid] = g_den[(size_t)gx * CH + tid];

    const unsigned offA = ((mbase + (lane & 15)) * MKS + (lane >> 4) * 8) * 2;
    const unsigned fAh = sptr(sAh) + offA;
    const unsigned fAl = sptr(sAl) + offA;
    const unsigned offB = ((((lane >> 3) & 1) * 8 + (lane & 7)) * KNS + nbase + ((lane >> 4) & 1) * 8) * 2;
    const unsigned fBh = sptr(sBh) + offB;
    const unsigned fBl = sptr(sBl) + offB;

    uint4* stAh = (uint4*)(sAh + arow * MKS + kseg);
    uint4* stAl = (uint4*)(sAl + arow * MKS + kseg);
    uint4* stBh0 = (uint4*)(sBh + (2 * pkr) * KNS + bn);
    uint4* stBl0 = (uint4*)(sBl + (2 * pkr) * KNS + bn);
    uint4* stBh1 = (uint4*)(sBh + (2 * pkr + 1) * KNS + bn);
    uint4* stBl1 = (uint4*)(sBl + (2 * pkr + 1) * KNS + bn);

    float acc[16][4];
#pragma unroll
    for (int i = 0; i < 16; ++i) acc[i][0] = acc[i][1] = acc[i][2] = acc[i][3] = 0.f;

    float bA[8], bB[8];
    {
        const float* r0p = Sb + (size_t)(2 * pkr) * DVDIM + bn;
        const float* r1p = Sb + (size_t)(2 * pkr + 1) * DVDIM + bn;
        *(float4*)&bA[0] = *(const float4*)r0p; *(float4*)&bA[4] = *(const float4*)(r0p + 4);
        *(float4*)&bB[0] = *(const float4*)r1p; *(float4*)&bB[4] = *(const float4*)(r1p + 4);
    }
    __syncthreads();

    // phase 1: q2 (on the fly) @ S, K = 256
    for (int s = 0; s < 8; ++s) {
        const int db = s * 32 + kseg;
        const float qi = qsm[arow * 17 + (db >> 4)] * 0.25f;
        float p[16];
#pragma unroll
        for (int j = 0; j < 16; ++j) p[j] = qi * qsm[arow * 17 + j];
        uint4 h4, l4;
        split8(p, h4, l4);     stAh[0] = h4; stAl[0] = l4;
        split8(p + 8, h4, l4); stAh[1] = h4; stAl[1] = l4;
        split8(bA, h4, l4); *stBh0 = h4; *stBl0 = l4;
        split8(bB, h4, l4); *stBh1 = h4; *stBl1 = l4;
        __syncthreads();
        if (s + 1 < 8) {
            const int d1 = (s + 1) * 32;
            const float* r0p = Sb + (size_t)(d1 + 2 * pkr) * DVDIM + bn;
            const float* r1p = Sb + (size_t)(d1 + 2 * pkr + 1) * DVDIM + bn;
            *(float4*)&bA[0] = *(const float4*)r0p; *(float4*)&bA[4] = *(const float4*)(r0p + 4);
            *(float4*)&bB[0] = *(const float4*)r1p; *(float4*)&bB[4] = *(const float4*)(r1p + 4);
        }
        mma_stage<false>(fAh, fAl, fBh, fBl, acc);
        __syncthreads();
    }

    // phase 2: A @ v, K = 128
    float4 raf[4];
#pragma unroll
    for (int u = 0; u < 4; ++u)
        raf[u] = *(const float4*)(Abp + (size_t)arow * CH + kseg + 4 * u);
    {
        const float* r0p = vb + (size_t)(2 * pkr) * DMODEL + bn;
        const float* r1p = vb + (size_t)(2 * pkr + 1) * DMODEL + bn;
        *(float4*)&bA[0] = *(const float4*)r0p; *(float4*)&bA[4] = *(const float4*)(r0p + 4);
        *(float4*)&bB[0] = *(const float4*)r1p; *(float4*)&bB[4] = *(const float4*)(r1p + 4);
    }
    for (int s = 0; s < 4; ++s) {
        uint4 h4, l4;
        split8((const float*)&raf[0], h4, l4); stAh[0] = h4; stAl[0] = l4;
        split8((const float*)&raf[2], h4, l4); stAh[1] = h4; stAl[1] = l4;
        split8(bA, h4, l4); *stBh0 = h4; *stBl0 = l4;
        split8(bB, h4, l4); *stBh1 = h4; *stBl1 = l4;
        __syncthreads();
        if (s + 1 < 4) {
            const int c0 = (s + 1) * 32;
#pragma unroll
            for (int u = 0; u < 4; ++u)
                raf[u] = *(const float4*)(Abp + (size_t)arow * CH + c0 + kseg + 4 * u);
            const float* r0p = vb + (size_t)(c0 + 2 * pkr) * DMODEL + bn;
            const float* r1p = vb + (size_t)(c0 + 2 * pkr + 1) * DMODEL + bn;
            *(float4*)&bA[0] = *(const float4*)r0p; *(float4*)&bA[4] = *(const float4*)(r0p + 4);
            *(float4*)&bB[0] = *(const float4*)r1p; *(float4*)&bB[4] = *(const float4*)(r1p + 4);
        }
        mma_stage<false>(fAh, fAl, fBh, fBl, acc);
        __syncthreads();
    }

    float* ob = g_oh + (size_t)(b * LLEN + ch * CH) * DMODEL + h * DVDIM;
#pragma unroll
    for (int mt = 0; mt < 4; ++mt) {
        const int r0 = mbase + mt * 16 + g;
        const float inv0 = 1.f / (dens[r0] + EPS);
        const float inv1 = 1.f / (dens[r0 + 8] + EPS);
#pragma unroll
        for (int nt = 0; nt < 4; ++nt) {
            const int col = nbase + nt * 8 + t * 2;
            const float* a4 = acc[mt * 4 + nt];
            *(float2*)(ob + (size_t)r0 * DMODEL + col)       = make_float2(a4[0] * inv0, a4[1] * inv0);
            *(float2*)(ob + (size_t)(r0 + 8) * DMODEL + col) = make_float2(a4[2] * inv1, a4[3] * inv1);
        }
    }
}

// ---------------- host pipeline ----------------
extern "C" void kernel_launch(void* const* d_in, const int* in_sizes, int n_in,
                              void* d_out, int out_size) {
    (void)in_sizes; (void)n_in; (void)out_size;
    const float* x   = (const float*)d_in[0];
    const float* Wq  = (const float*)d_in[1];
    const float* Wk  = (const float*)d_in[2];
    const float* Wv  = (const float*)d_in[3];
    const float* Wo  = (const float*)d_in[4];
    const float* lqg = (const float*)d_in[5];
    const float* lqb = (const float*)d_in[6];
    const float* lkg = (const float*)d_in[7];
    const float* lkb = (const float*)d_in[8];
    float* out = (float*)d_out;

    float *vp, *ohp;
    cudaGetSymbolAddress((void**)&vp, g_v);
    cudaGetSymbolAddress((void**)&ohp, g_oh);

    projqk_kernel<<<dim3(2, 32, 2), 256>>>(x, Wq, Wk);
    proj_kernel<<<dim3(12, 32), 256>>>(x, Wv, vp, DMODEL, DMODEL);
    ln_kernel<<<(2 * NTOK) / 8, 256>>>(lqg, lqb, lkg, lkb);
    kvstate_bf16<<<BB * HH * NC * 2, 256>>>();
    {
        const int total = BB * HH * D2 * DVDIM + BB * HH * D2;
        prefix_kernel<<<(total + 255) / 256, 256>>>();
    }
    attn_a_new<<<BB * HH * NC, 256>>>();
    attn_b_bf16<<<BB * HH * NC, 256>>>();
    proj_kernel<<<dim3(12, 32), 256>>>(ohp, Wo, out, DMODEL, DMODEL);
}